// round 3
// baseline (speedup 1.0000x reference)
#include <cuda_runtime.h>

// ---------------- problem constants ----------------
#define BN    4        // batch
#define TN    32768    // time
#define LCN   128      // cond length
#define HOPN  256      // T / Lc
#define HIDN  128      // hidden
#define NLN   4        // layers
#define CONDN 512      // cond channels
#define CKN   384      // HID * KER (reduction dim of LVC / dilconv)

// ---------------- scratch (device globals; no allocation allowed) ----------
// kbuf layout: [b][layer][l][ck = cin*3+k][cout]  -> LVC A-operand is contiguous
__device__ __align__(128) float g_kbuf[(size_t)BN * NLN * LCN * CKN * HIDN]; // 402 MB
__device__ __align__(128) float g_bbuf[BN * NLN * HIDN * LCN];               // [b][i*128+o][l]
__device__ __align__(128) float g_h0[(size_t)BN * HIDN * TN];                // 67 MB
__device__ __align__(128) float g_h1[(size_t)BN * HIDN * TN];                // 67 MB
__device__ __align__(128) float g_wT[NLN * CKN * HIDN];                      // block_w transposed

__device__ __forceinline__ float lrelu(float v, float s) { return v >= 0.f ? v : s * v; }

// ============================================================================
// 1) Kernel predictor GEMM:  kp[b, r, l] = sum_c kernel_w[r,c]*cond[b,c,l] + kernel_b[r]
//    with row permutation m = (cin*3+k)*128 + cout  (source r = ((i*128+cin)*128+cout)*3+k)
//    Block: 128 l x 128 m, K = 512.  grid = (b=4, mblk=1536) -> one mblk == one (i, ck).
// ============================================================================
__global__ __launch_bounds__(256) void kpred_gemm(const float* __restrict__ kw,
                                                  const float* __restrict__ kb,
                                                  const float* __restrict__ cond)
{
    __shared__ float As[16][132];  // [kk][l]     (cond)
    __shared__ float Bs[16][132];  // [kk][cout]  (kernel_w, transposed on load)

    const int b    = blockIdx.x;
    const int mblk = blockIdx.y;          // 0..1535
    const int il   = mblk / CKN;          // layer
    const int ck   = mblk - il * CKN;     // cin*3+k
    const int cin  = ck / 3;
    const int kq   = ck - cin * 3;
    const int rbase = il * 49152 + cin * 384 + kq;     // r(m) = rbase + 3*m

    const float* condb = cond + (size_t)b * CONDN * LCN;

    const int tid = threadIdx.x;
    const int tx  = tid & 15;   // m (cout) axis
    const int ty  = tid >> 4;   // l axis

    float acc[8][8];
#pragma unroll
    for (int i = 0; i < 8; i++)
#pragma unroll
        for (int j = 0; j < 8; j++) acc[i][j] = 0.f;

    for (int k0 = 0; k0 < CONDN; k0 += 16) {
        // load cond tile (coalesced)
#pragma unroll
        for (int it = 0; it < 2; it++) {
            int idx = tid + it * 256;              // 0..511
            int kk = idx >> 5, lq = idx & 31;
            float4 v = *(const float4*)(condb + (size_t)(k0 + kk) * LCN + lq * 4);
            *(float4*)&As[kk][lq * 4] = v;
        }
        // load kernel_w rows (row-contiguous), store transposed
#pragma unroll
        for (int it = 0; it < 2; it++) {
            int idx = tid + it * 256;              // 0..511
            int m = idx >> 2, q = idx & 3;
            const float* rp = kw + (size_t)(rbase + 3 * m) * CONDN + k0 + q * 4;
            float4 v = *(const float4*)rp;
            Bs[q * 4 + 0][m] = v.x; Bs[q * 4 + 1][m] = v.y;
            Bs[q * 4 + 2][m] = v.z; Bs[q * 4 + 3][m] = v.w;
        }
        __syncthreads();
#pragma unroll
        for (int kk = 0; kk < 16; kk++) {
            float a[8], w[8];
            *(float4*)(a)     = *(const float4*)&As[kk][ty * 8];
            *(float4*)(a + 4) = *(const float4*)&As[kk][ty * 8 + 4];
            *(float4*)(w)     = *(const float4*)&Bs[kk][tx * 8];
            *(float4*)(w + 4) = *(const float4*)&Bs[kk][tx * 8 + 4];
#pragma unroll
            for (int i = 0; i < 8; i++)
#pragma unroll
                for (int j = 0; j < 8; j++) acc[i][j] += a[i] * w[j];
        }
        __syncthreads();
    }

    float bias[8];
#pragma unroll
    for (int j = 0; j < 8; j++) bias[j] = kb[rbase + 3 * (tx * 8 + j)];

    const size_t dbase = ((size_t)(b * NLN + il) * LCN) * ((size_t)CKN * HIDN) + (size_t)ck * HIDN;
#pragma unroll
    for (int i = 0; i < 8; i++) {
        int l = ty * 8 + i;
        float* dp = g_kbuf + dbase + (size_t)l * (CKN * HIDN) + tx * 8;
        float4 v0, v1;
        v0.x = acc[i][0] + bias[0]; v0.y = acc[i][1] + bias[1];
        v0.z = acc[i][2] + bias[2]; v0.w = acc[i][3] + bias[3];
        v1.x = acc[i][4] + bias[4]; v1.y = acc[i][5] + bias[5];
        v1.z = acc[i][6] + bias[6]; v1.w = acc[i][7] + bias[7];
        *(float4*)dp = v0; *(float4*)(dp + 4) = v1;
    }
}

// ============================================================================
// 2) Bias predictor (tiny GEMM): bbuf[b][r][l] = sum_c biasp_w[r,c]*cond[b,c,l] + biasp_b[r]
//    grid (r=512, b=4), 128 threads (one per l)
// ============================================================================
__global__ void bias_pred(const float* __restrict__ bw, const float* __restrict__ bb,
                          const float* __restrict__ cond)
{
    __shared__ float ws[CONDN];
    const int r = blockIdx.x, b = blockIdx.y;
    const int l = threadIdx.x;
    for (int c = l; c < CONDN; c += 128) ws[c] = bw[(size_t)r * CONDN + c];
    __syncthreads();
    const float* condb = cond + (size_t)b * CONDN * LCN + l;
    float acc = bb[r];
#pragma unroll 8
    for (int c = 0; c < CONDN; c++) acc += ws[c] * condb[(size_t)c * LCN];
    g_bbuf[((size_t)b * (NLN * HIDN) + r) * LCN + l] = acc;
}

// ============================================================================
// 3) transpose block_w: g_wT[i][(cin*3+k)*128 + o] = block_w[i][o][cin][k]
// ============================================================================
__global__ void transpose_w(const float* __restrict__ bw)
{
    int idx = blockIdx.x * blockDim.x + threadIdx.x;
    if (idx >= NLN * CKN * HIDN) return;
    int il = idx / (CKN * HIDN);
    int rem = idx - il * (CKN * HIDN);
    int ck = rem >> 7, o = rem & 127;
    int cin = ck / 3, k = ck - cin * 3;
    g_wT[idx] = bw[((size_t)(il * HIDN + o) * HIDN + cin) * 3 + k];
}

// ============================================================================
// 4) preconv: h0[b][ch][t] = lrelu(pre_w[ch]*x[b][t] + pre_b[ch], 0.2)
// ============================================================================
__global__ void preconv(const float* __restrict__ x, const float* __restrict__ pw,
                        const float* __restrict__ pb)
{
    int idx = blockIdx.x * blockDim.x + threadIdx.x;        // over B*HID*T/4
    const int T4 = TN / 4;
    int t4 = idx % T4;
    int ch = (idx / T4) & (HIDN - 1);
    int b  = idx / (T4 * HIDN);
    float w = pw[ch], bi = pb[ch];
    float4 xv = *(const float4*)(x + (size_t)b * TN + (size_t)t4 * 4);
    float4 o;
    o.x = lrelu(w * xv.x + bi, 0.2f);
    o.y = lrelu(w * xv.y + bi, 0.2f);
    o.z = lrelu(w * xv.z + bi, 0.2f);
    o.w = lrelu(w * xv.w + bi, 0.2f);
    *(float4*)(g_h0 + ((size_t)(b * HIDN + ch)) * TN + (size_t)t4 * 4) = o;
}

// ============================================================================
// 5) LVC: per (b,l) GEMM  out[o,s] = lrelu( sum_ck W[ck][o]*h[cin][t0+s+k-1] + bias[o], 3.0 )
//    reads g_h0, writes g_h1.  grid (sh=2, l=128, b=4); tile 128 o x 128 s, K=384.
// ============================================================================
__global__ __launch_bounds__(256) void lvc_gemm(int il)
{
    __shared__ float Ws[16][132];  // [kk][o]
    __shared__ float Hs[16][132];  // [kk][s]
    __shared__ float bsm[128];

    const int sh = blockIdx.x;       // s-half
    const int l  = blockIdx.y;
    const int b  = blockIdx.z;
    const int t0 = l * HOPN + sh * 128;

    const float* Wb = g_kbuf + ((size_t)(b * NLN + il) * LCN + l) * ((size_t)CKN * HIDN);
    const float* hb = g_h0 + (size_t)b * HIDN * TN;

    const int tid = threadIdx.x;
    const int tx = tid & 15;   // s axis
    const int ty = tid >> 4;   // o axis
    if (tid < 128)
        bsm[tid] = g_bbuf[((size_t)b * (NLN * HIDN) + il * HIDN + tid) * LCN + l];

    float acc[8][8];
#pragma unroll
    for (int i = 0; i < 8; i++)
#pragma unroll
        for (int j = 0; j < 8; j++) acc[i][j] = 0.f;

    for (int c0 = 0; c0 < CKN; c0 += 16) {
#pragma unroll
        for (int it = 0; it < 2; it++) {
            int idx = tid + it * 256;
            int kk = idx >> 5, oq = idx & 31;
            *(float4*)&Ws[kk][oq * 4] = *(const float4*)(Wb + (size_t)(c0 + kk) * HIDN + oq * 4);
        }
#pragma unroll
        for (int it = 0; it < 8; it++) {
            int idx = tid + it * 256;          // 0..2047
            int kk = idx >> 7, s = idx & 127;
            int ck2 = c0 + kk;
            int cin = ck2 / 3, k = ck2 - cin * 3;
            int t = t0 + s + k - 1;
            Hs[kk][s] = (t >= 0 && t < TN) ? hb[(size_t)cin * TN + t] : 0.f;
        }
        __syncthreads();
#pragma unroll
        for (int kk = 0; kk < 16; kk++) {
            float a[8], h[8];
            *(float4*)(a)     = *(const float4*)&Ws[kk][ty * 8];
            *(float4*)(a + 4) = *(const float4*)&Ws[kk][ty * 8 + 4];
            *(float4*)(h)     = *(const float4*)&Hs[kk][tx * 8];
            *(float4*)(h + 4) = *(const float4*)&Hs[kk][tx * 8 + 4];
#pragma unroll
            for (int i = 0; i < 8; i++)
#pragma unroll
                for (int j = 0; j < 8; j++) acc[i][j] += a[i] * h[j];
        }
        __syncthreads();
    }

#pragma unroll
    for (int i = 0; i < 8; i++) {
        int o = ty * 8 + i;
        float bi = bsm[o];
        float* dp = g_h1 + ((size_t)(b * HIDN + o)) * TN + t0 + tx * 8;
        float4 v0, v1;
        v0.x = lrelu(acc[i][0] + bi, 3.f); v0.y = lrelu(acc[i][1] + bi, 3.f);
        v0.z = lrelu(acc[i][2] + bi, 3.f); v0.w = lrelu(acc[i][3] + bi, 3.f);
        v1.x = lrelu(acc[i][4] + bi, 3.f); v1.y = lrelu(acc[i][5] + bi, 3.f);
        v1.z = lrelu(acc[i][6] + bi, 3.f); v1.w = lrelu(acc[i][7] + bi, 3.f);
        *(float4*)dp = v0; *(float4*)(dp + 4) = v1;
    }
}

// ============================================================================
// 6) dilated conv: out[o,t] = lrelu( sum_ck wT[i][ck][o]*h[cin][t+(k-1)*d] + bb[i][o], 3.0 )
//    reads g_h1, writes g_h0. grid (tblk=256, b=4); tile 128 o x 128 t, K=384.
// ============================================================================
__global__ __launch_bounds__(256) void dil_gemm(int il, int d, const float* __restrict__ blockb)
{
    __shared__ float Ws[16][132];
    __shared__ float Hs[16][132];
    __shared__ float bsm[128];

    const int t0 = blockIdx.x * 128;
    const int b  = blockIdx.y;
    const float* Wb = g_wT + (size_t)il * CKN * HIDN;
    const float* hb = g_h1 + (size_t)b * HIDN * TN;

    const int tid = threadIdx.x;
    const int tx = tid & 15;   // t axis
    const int ty = tid >> 4;   // o axis
    if (tid < 128) bsm[tid] = blockb[il * HIDN + tid];

    float acc[8][8];
#pragma unroll
    for (int i = 0; i < 8; i++)
#pragma unroll
        for (int j = 0; j < 8; j++) acc[i][j] = 0.f;

    for (int c0 = 0; c0 < CKN; c0 += 16) {
#pragma unroll
        for (int it = 0; it < 2; it++) {
            int idx = tid + it * 256;
            int kk = idx >> 5, oq = idx & 31;
            *(float4*)&Ws[kk][oq * 4] = *(const float4*)(Wb + (size_t)(c0 + kk) * HIDN + oq * 4);
        }
#pragma unroll
        for (int it = 0; it < 8; it++) {
            int idx = tid + it * 256;
            int kk = idx >> 7, s = idx & 127;
            int ck2 = c0 + kk;
            int cin = ck2 / 3, k = ck2 - cin * 3;
            int t = t0 + s + (k - 1) * d;
            Hs[kk][s] = (t >= 0 && t < TN) ? hb[(size_t)cin * TN + t] : 0.f;
        }
        __syncthreads();
#pragma unroll
        for (int kk = 0; kk < 16; kk++) {
            float a[8], h[8];
            *(float4*)(a)     = *(const float4*)&Ws[kk][ty * 8];
            *(float4*)(a + 4) = *(const float4*)&Ws[kk][ty * 8 + 4];
            *(float4*)(h)     = *(const float4*)&Hs[kk][tx * 8];
            *(float4*)(h + 4) = *(const float4*)&Hs[kk][tx * 8 + 4];
#pragma unroll
            for (int i = 0; i < 8; i++)
#pragma unroll
                for (int j = 0; j < 8; j++) acc[i][j] += a[i] * h[j];
        }
        __syncthreads();
    }

#pragma unroll
    for (int i = 0; i < 8; i++) {
        int o = ty * 8 + i;
        float bi = bsm[o];
        float* dp = g_h0 + ((size_t)(b * HIDN + o)) * TN + t0 + tx * 8;
        float4 v0, v1;
        v0.x = lrelu(acc[i][0] + bi, 3.f); v0.y = lrelu(acc[i][1] + bi, 3.f);
        v0.z = lrelu(acc[i][2] + bi, 3.f); v0.w = lrelu(acc[i][3] + bi, 3.f);
        v1.x = lrelu(acc[i][4] + bi, 3.f); v1.y = lrelu(acc[i][5] + bi, 3.f);
        v1.z = lrelu(acc[i][6] + bi, 3.f); v1.w = lrelu(acc[i][7] + bi, 3.f);
        *(float4*)dp = v0; *(float4*)(dp + 4) = v1;
    }
}

// ============================================================================
// 7) postconv: out[b][t] = sum_o post_w[o]*h0[b][o][t] + post_b
// ============================================================================
__global__ void postconv(const float* __restrict__ pw, const float* __restrict__ pb,
                         float* __restrict__ out)
{
    __shared__ float ws[HIDN];
    const int t = blockIdx.x * 256 + threadIdx.x;
    const int b = blockIdx.y;
    if (threadIdx.x < HIDN) ws[threadIdx.x] = pw[threadIdx.x];
    __syncthreads();
    float acc = pb[0];
    const float* hb = g_h0 + (size_t)b * HIDN * TN + t;
#pragma unroll 8
    for (int o = 0; o < HIDN; o++) acc += ws[o] * hb[(size_t)o * TN];
    out[(size_t)b * TN + t] = acc;
}

// ============================================================================
extern "C" void kernel_launch(void* const* d_in, const int* in_sizes, int n_in,
                              void* d_out, int out_size)
{
    const float* x        = (const float*)d_in[0];
    const float* c        = (const float*)d_in[1];
    const float* kernel_w = (const float*)d_in[2];
    const float* kernel_b = (const float*)d_in[3];
    const float* biasp_w  = (const float*)d_in[4];
    const float* biasp_b  = (const float*)d_in[5];
    const float* pre_w    = (const float*)d_in[6];
    const float* pre_b    = (const float*)d_in[7];
    const float* block_w  = (const float*)d_in[8];
    const float* block_b  = (const float*)d_in[9];
    const float* post_w   = (const float*)d_in[10];
    const float* post_b   = (const float*)d_in[11];
    float* out = (float*)d_out;

    kpred_gemm<<<dim3(BN, (NLN * CKN)), 256>>>(kernel_w, kernel_b, c);
    bias_pred<<<dim3(NLN * HIDN, BN), 128>>>(biasp_w, biasp_b, c);
    transpose_w<<<(NLN * CKN * HIDN + 255) / 256, 256>>>(block_w);
    preconv<<<(BN * HIDN * TN / 4) / 256, 256>>>(x, pre_w, pre_b);

    const int dils[NLN] = {1, 3, 9, 27};
    for (int i = 0; i < NLN; i++) {
        lvc_gemm<<<dim3(2, LCN, BN), 256>>>(i);
        dil_gemm<<<dim3(TN / 128, BN), 256>>>(i, dils[i], block_b);
    }
    postconv<<<dim3(TN / 256, BN), 256>>>(post_w, post_b, out);
}

// round 5
// speedup vs baseline: 1.4898x; 1.4898x over previous
#include <cuda_runtime.h>

// ---------------- problem constants ----------------
#define BN    4
#define TN    32768
#define LCN   128
#define HOPN  256
#define HIDN  128
#define NLN   4
#define CONDN 512
#define CKN   384
#define KT    16     // K tile
#define SA    136    // smem row stride (conflict-free fragment loads)

// ---------------- scratch ----------------
__device__ __align__(128) float g_kbuf[(size_t)BN * NLN * LCN * CKN * HIDN]; // [b][il][l][ck][cout]
__device__ __align__(128) float g_bbuf[BN * NLN * HIDN * LCN];
__device__ __align__(128) float g_h0[(size_t)BN * HIDN * TN];
__device__ __align__(128) float g_h1[(size_t)BN * HIDN * TN];
__device__ __align__(128) float g_wT[NLN * CKN * HIDN];

__device__ __forceinline__ float lrelu(float v, float s) { return v >= 0.f ? v : s * v; }

// tf32 split: hi = truncate-to-tf32(x) (exact in fp32), lo = x - hi (exact)
__device__ __forceinline__ void split_tf32(float x, unsigned& hi, unsigned& lo)
{
    unsigned u = __float_as_uint(x) & 0xFFFFE000u;
    hi = u;
    lo = __float_as_uint(x - __uint_as_float(u));
}

__device__ __forceinline__ void mma8(float* c, unsigned a0, unsigned a1, unsigned a2, unsigned a3,
                                     unsigned b0, unsigned b1)
{
    asm volatile(
        "mma.sync.aligned.m16n8k8.row.col.f32.tf32.tf32.f32 "
        "{%0,%1,%2,%3}, {%4,%5,%6,%7}, {%8,%9}, {%0,%1,%2,%3};\n"
        : "+f"(c[0]), "+f"(c[1]), "+f"(c[2]), "+f"(c[3])
        : "r"(a0), "r"(a1), "r"(a2), "r"(a3), "r"(b0), "r"(b1));
}

// One 128x128 x K=16 tile step with 3xTF32. As=[k][m] (stride SA), Bs=[k][n] (stride SA).
// Warp (wm in 0..1, wn in 0..3) owns m: wm*64..+64, n: wn*32..+32.
__device__ __forceinline__ void tile_mma(const float* __restrict__ As,
                                         const float* __restrict__ Bs,
                                         int wm, int wn, int g, int tg,
                                         float (&acc)[4][4][4])
{
#pragma unroll
    for (int ks = 0; ks < 2; ks++) {
        const float* Ak0 = As + (ks * 8 + tg) * SA;
        const float* Ak4 = Ak0 + 4 * SA;
        const float* Bk0 = Bs + (ks * 8 + tg) * SA + wn * 32 + g;
        const float* Bk4 = Bk0 + 4 * SA;

        unsigned bhi[4][2], blo[4][2];
#pragma unroll
        for (int fn = 0; fn < 4; fn++) {
            split_tf32(Bk0[fn * 8], bhi[fn][0], blo[fn][0]);
            split_tf32(Bk4[fn * 8], bhi[fn][1], blo[fn][1]);
        }
#pragma unroll
        for (int fm = 0; fm < 4; fm++) {
            const int m0 = wm * 64 + fm * 16 + g;
            unsigned ahi[4], alo[4];
            split_tf32(Ak0[m0],     ahi[0], alo[0]);
            split_tf32(Ak0[m0 + 8], ahi[1], alo[1]);
            split_tf32(Ak4[m0],     ahi[2], alo[2]);
            split_tf32(Ak4[m0 + 8], ahi[3], alo[3]);
#pragma unroll
            for (int fn = 0; fn < 4; fn++) {
                mma8(acc[fm][fn], ahi[0], ahi[1], ahi[2], ahi[3], bhi[fn][0], bhi[fn][1]);
                mma8(acc[fm][fn], alo[0], alo[1], alo[2], alo[3], bhi[fn][0], bhi[fn][1]);
                mma8(acc[fm][fn], ahi[0], ahi[1], ahi[2], ahi[3], blo[fn][0], blo[fn][1]);
            }
        }
    }
}

// ============================================================================
// 1) Kernel predictor GEMM (tensor): m = l (cond), n = cout (kernel_w), K = 512
//    one block per (b, il, ck): C[l][cout] -> g_kbuf[b][il][l][ck][cout]
// ============================================================================
__global__ __launch_bounds__(256, 2) void kpred_gemm(const float* __restrict__ kw,
                                                     const float* __restrict__ kb,
                                                     const float* __restrict__ cond)
{
    __shared__ __align__(16) float As[KT * SA];   // [k][l]
    __shared__ __align__(16) float Bs[KT * SA];   // [k][cout]
    __shared__ float bsm[128];

    const int b    = blockIdx.x;
    const int mblk = blockIdx.y;
    const int il   = mblk / CKN;
    const int ck   = mblk - il * CKN;
    const int cin  = ck / 3;
    const int kq   = ck - cin * 3;
    const int rbase = il * 49152 + cin * 384 + kq;   // r(cout) = rbase + 3*cout

    const float* condb = cond + (size_t)b * CONDN * LCN;

    const int tid  = threadIdx.x;
    const int wid  = tid >> 5;
    const int lane = tid & 31;
    const int g    = lane >> 2;
    const int tg   = lane & 3;
    const int wm   = wid & 1;
    const int wn   = wid >> 1;

    if (tid < 128) bsm[tid] = kb[rbase + 3 * tid];

    float acc[4][4][4];
#pragma unroll
    for (int i = 0; i < 4; i++)
#pragma unroll
        for (int j = 0; j < 4; j++)
#pragma unroll
            for (int q = 0; q < 4; q++) acc[i][j][q] = 0.f;

    for (int k0 = 0; k0 < CONDN; k0 += KT) {
#pragma unroll
        for (int it = 0; it < 2; it++) {
            int idx = tid + it * 256;
            int kk = idx >> 5, lq = idx & 31;
            float4 v = *(const float4*)(condb + (size_t)(k0 + kk) * LCN + lq * 4);
            *(float4*)&As[kk * SA + lq * 4] = v;
        }
#pragma unroll
        for (int it = 0; it < 2; it++) {
            int idx = tid + it * 256;
            int m = idx >> 2, q = idx & 3;
            const float* rp = kw + (size_t)(rbase + 3 * m) * CONDN + k0 + q * 4;
            float4 v = *(const float4*)rp;
            Bs[(q * 4 + 0) * SA + m] = v.x; Bs[(q * 4 + 1) * SA + m] = v.y;
            Bs[(q * 4 + 2) * SA + m] = v.z; Bs[(q * 4 + 3) * SA + m] = v.w;
        }
        __syncthreads();
        tile_mma(As, Bs, wm, wn, g, tg, acc);
        __syncthreads();
    }

    const size_t base = ((size_t)(b * NLN + il) * LCN) * ((size_t)CKN * HIDN) + (size_t)ck * HIDN;
#pragma unroll
    for (int fm = 0; fm < 4; fm++) {
        const int l0 = wm * 64 + fm * 16 + g;
        float* row0 = g_kbuf + base + (size_t)l0 * (CKN * HIDN);
        float* row1 = row0 + (size_t)8 * (CKN * HIDN);
#pragma unroll
        for (int fn = 0; fn < 4; fn++) {
            const int n0 = wn * 32 + fn * 8 + 2 * tg;
            float b0 = bsm[n0], b1 = bsm[n0 + 1];
            float2 v0, v1;
            v0.x = acc[fm][fn][0] + b0; v0.y = acc[fm][fn][1] + b1;
            v1.x = acc[fm][fn][2] + b0; v1.y = acc[fm][fn][3] + b1;
            *(float2*)(row0 + n0) = v0;
            *(float2*)(row1 + n0) = v1;
        }
    }
}

// ============================================================================
// 2) Bias predictor (unchanged)
// ============================================================================
__global__ void bias_pred(const float* __restrict__ bw, const float* __restrict__ bb,
                          const float* __restrict__ cond)
{
    __shared__ float ws[CONDN];
    const int r = blockIdx.x, b = blockIdx.y;
    const int l = threadIdx.x;
    for (int c = l; c < CONDN; c += 128) ws[c] = bw[(size_t)r * CONDN + c];
    __syncthreads();
    const float* condb = cond + (size_t)b * CONDN * LCN + l;
    float acc = bb[r];
#pragma unroll 8
    for (int c = 0; c < CONDN; c++) acc += ws[c] * condb[(size_t)c * LCN];
    g_bbuf[((size_t)b * (NLN * HIDN) + r) * LCN + l] = acc;
}

// ============================================================================
// 3) transpose block_w (unchanged)
// ============================================================================
__global__ void transpose_w(const float* __restrict__ bw)
{
    int idx = blockIdx.x * blockDim.x + threadIdx.x;
    if (idx >= NLN * CKN * HIDN) return;
    int il = idx / (CKN * HIDN);
    int rem = idx - il * (CKN * HIDN);
    int ck = rem >> 7, o = rem & 127;
    int cin = ck / 3, k = ck - cin * 3;
    g_wT[idx] = bw[((size_t)(il * HIDN + o) * HIDN + cin) * 3 + k];
}

// ============================================================================
// 4) preconv (unchanged)
// ============================================================================
__global__ void preconv(const float* __restrict__ x, const float* __restrict__ pw,
                        const float* __restrict__ pb)
{
    int idx = blockIdx.x * blockDim.x + threadIdx.x;
    const int T4 = TN / 4;
    int t4 = idx % T4;
    int ch = (idx / T4) & (HIDN - 1);
    int b  = idx / (T4 * HIDN);
    float w = pw[ch], bi = pb[ch];
    float4 xv = *(const float4*)(x + (size_t)b * TN + (size_t)t4 * 4);
    float4 o;
    o.x = lrelu(w * xv.x + bi, 0.2f);
    o.y = lrelu(w * xv.y + bi, 0.2f);
    o.z = lrelu(w * xv.z + bi, 0.2f);
    o.w = lrelu(w * xv.w + bi, 0.2f);
    *(float4*)(g_h0 + ((size_t)(b * HIDN + ch)) * TN + (size_t)t4 * 4) = o;
}

// ============================================================================
// 5) LVC (tensor): m = o, n = s, K = 384.  g_h0 -> g_h1
// ============================================================================
__global__ __launch_bounds__(256, 2) void lvc_gemm(int il)
{
    __shared__ __align__(16) float As[KT * SA];   // [k][o]  (W)
    __shared__ __align__(16) float Bs[KT * SA];   // [k][s]  (H gather)
    __shared__ float bsm[128];

    const int sh = blockIdx.x;
    const int l  = blockIdx.y;
    const int b  = blockIdx.z;
    const int t0 = l * HOPN + sh * 128;

    const float* Wb = g_kbuf + ((size_t)(b * NLN + il) * LCN + l) * ((size_t)CKN * HIDN);
    const float* hb = g_h0 + (size_t)b * HIDN * TN;

    const int tid  = threadIdx.x;
    const int wid  = tid >> 5;
    const int lane = tid & 31;
    const int g    = lane >> 2;
    const int tg   = lane & 3;
    const int wm   = wid & 1;
    const int wn   = wid >> 1;

    if (tid < 128)
        bsm[tid] = g_bbuf[((size_t)b * (NLN * HIDN) + il * HIDN + tid) * LCN + l];

    float acc[4][4][4];
#pragma unroll
    for (int i = 0; i < 4; i++)
#pragma unroll
        for (int j = 0; j < 4; j++)
#pragma unroll
            for (int q = 0; q < 4; q++) acc[i][j][q] = 0.f;

    for (int c0 = 0; c0 < CKN; c0 += KT) {
#pragma unroll
        for (int it = 0; it < 2; it++) {
            int idx = tid + it * 256;
            int kk = idx >> 5, oq = idx & 31;
            *(float4*)&As[kk * SA + oq * 4] = *(const float4*)(Wb + (size_t)(c0 + kk) * HIDN + oq * 4);
        }
#pragma unroll
        for (int it = 0; it < 8; it++) {
            int idx = tid + it * 256;
            int kk = idx >> 7, s = idx & 127;
            int ck2 = c0 + kk;
            int cin = ck2 / 3, k = ck2 - cin * 3;
            int t = t0 + s + k - 1;
            Bs[kk * SA + s] = (t >= 0 && t < TN) ? hb[(size_t)cin * TN + t] : 0.f;
        }
        __syncthreads();
        tile_mma(As, Bs, wm, wn, g, tg, acc);
        __syncthreads();
    }

#pragma unroll
    for (int fm = 0; fm < 4; fm++) {
        const int o0 = wm * 64 + fm * 16 + g;
        float b0 = bsm[o0], b1 = bsm[o0 + 8];
        float* row0 = g_h1 + ((size_t)(b * HIDN + o0)) * TN + t0;
        float* row1 = row0 + (size_t)8 * TN;
#pragma unroll
        for (int fn = 0; fn < 4; fn++) {
            const int n0 = wn * 32 + fn * 8 + 2 * tg;
            float2 v0, v1;
            v0.x = lrelu(acc[fm][fn][0] + b0, 3.f);
            v0.y = lrelu(acc[fm][fn][1] + b0, 3.f);
            v1.x = lrelu(acc[fm][fn][2] + b1, 3.f);
            v1.y = lrelu(acc[fm][fn][3] + b1, 3.f);
            *(float2*)(row0 + n0) = v0;
            *(float2*)(row1 + n0) = v1;
        }
    }
}

// ============================================================================
// 6) dilated conv (tensor): m = o, n = t, K = 384.  g_h1 -> g_h0
// ============================================================================
__global__ __launch_bounds__(256, 2) void dil_gemm(int il, int d, const float* __restrict__ blockb)
{
    __shared__ __align__(16) float As[KT * SA];
    __shared__ __align__(16) float Bs[KT * SA];
    __shared__ float bsm[128];

    const int t0 = blockIdx.x * 128;
    const int b  = blockIdx.y;
    const float* Wb = g_wT + (size_t)il * CKN * HIDN;
    const float* hb = g_h1 + (size_t)b * HIDN * TN;

    const int tid  = threadIdx.x;
    const int wid  = tid >> 5;
    const int lane = tid & 31;
    const int g    = lane >> 2;
    const int tg   = lane & 3;
    const int wm   = wid & 1;
    const int wn   = wid >> 1;

    if (tid < 128) bsm[tid] = blockb[il * HIDN + tid];

    float acc[4][4][4];
#pragma unroll
    for (int i = 0; i < 4; i++)
#pragma unroll
        for (int j = 0; j < 4; j++)
#pragma unroll
            for (int q = 0; q < 4; q++) acc[i][j][q] = 0.f;

    for (int c0 = 0; c0 < CKN; c0 += KT) {
#pragma unroll
        for (int it = 0; it < 2; it++) {
            int idx = tid + it * 256;
            int kk = idx >> 5, oq = idx & 31;
            *(float4*)&As[kk * SA + oq * 4] = *(const float4*)(Wb + (size_t)(c0 + kk) * HIDN + oq * 4);
        }
#pragma unroll
        for (int it = 0; it < 8; it++) {
            int idx = tid + it * 256;
            int kk = idx >> 7, s = idx & 127;
            int ck2 = c0 + kk;
            int cin = ck2 / 3, k = ck2 - cin * 3;
            int t = t0 + s + (k - 1) * d;
            Bs[kk * SA + s] = (t >= 0 && t < TN) ? hb[(size_t)cin * TN + t] : 0.f;
        }
        __syncthreads();
        tile_mma(As, Bs, wm, wn, g, tg, acc);
        __syncthreads();
    }

#pragma unroll
    for (int fm = 0; fm < 4; fm++) {
        const int o0 = wm * 64 + fm * 16 + g;
        float b0 = bsm[o0], b1 = bsm[o0 + 8];
        float* row0 = g_h0 + ((size_t)(b * HIDN + o0)) * TN + t0;
        float* row1 = row0 + (size_t)8 * TN;
#pragma unroll
        for (int fn = 0; fn < 4; fn++) {
            const int n0 = wn * 32 + fn * 8 + 2 * tg;
            float2 v0, v1;
            v0.x = lrelu(acc[fm][fn][0] + b0, 3.f);
            v0.y = lrelu(acc[fm][fn][1] + b0, 3.f);
            v1.x = lrelu(acc[fm][fn][2] + b1, 3.f);
            v1.y = lrelu(acc[fm][fn][3] + b1, 3.f);
            *(float2*)(row0 + n0) = v0;
            *(float2*)(row1 + n0) = v1;
        }
    }
}

// ============================================================================
// 7) postconv (unchanged)
// ============================================================================
__global__ void postconv(const float* __restrict__ pw, const float* __restrict__ pb,
                         float* __restrict__ out)
{
    __shared__ float ws[HIDN];
    const int t = blockIdx.x * 256 + threadIdx.x;
    const int b = blockIdx.y;
    if (threadIdx.x < HIDN) ws[threadIdx.x] = pw[threadIdx.x];
    __syncthreads();
    float acc = pb[0];
    const float* hb = g_h0 + (size_t)b * HIDN * TN + t;
#pragma unroll 8
    for (int o = 0; o < HIDN; o++) acc += ws[o] * hb[(size_t)o * TN];
    out[(size_t)b * TN + t] = acc;
}

// ============================================================================
extern "C" void kernel_launch(void* const* d_in, const int* in_sizes, int n_in,
                              void* d_out, int out_size)
{
    const float* x        = (const float*)d_in[0];
    const float* c        = (const float*)d_in[1];
    const float* kernel_w = (const float*)d_in[2];
    const float* kernel_b = (const float*)d_in[3];
    const float* biasp_w  = (const float*)d_in[4];
    const float* biasp_b  = (const float*)d_in[5];
    const float* pre_w    = (const float*)d_in[6];
    const float* pre_b    = (const float*)d_in[7];
    const float* block_w  = (const float*)d_in[8];
    const float* block_b  = (const float*)d_in[9];
    const float* post_w   = (const float*)d_in[10];
    const float* post_b   = (const float*)d_in[11];
    float* out = (float*)d_out;

    kpred_gemm<<<dim3(BN, (NLN * CKN)), 256>>>(kernel_w, kernel_b, c);
    bias_pred<<<dim3(NLN * HIDN, BN), 128>>>(biasp_w, biasp_b, c);
    transpose_w<<<(NLN * CKN * HIDN + 255) / 256, 256>>>(block_w);
    preconv<<<(BN * HIDN * TN / 4) / 256, 256>>>(x, pre_w, pre_b);

    const int dils[NLN] = {1, 3, 9, 27};
    for (int i = 0; i < NLN; i++) {
        lvc_gemm<<<dim3(2, LCN, BN), 256>>>(i);
        dil_gemm<<<dim3(TN / 128, BN), 256>>>(i, dils[i], block_b);
    }
    postconv<<<dim3(TN / 256, BN), 256>>>(post_w, post_b, out);
}

// round 8
// speedup vs baseline: 1.6009x; 1.0746x over previous
#include <cuda_runtime.h>

// ---------------- problem constants ----------------
#define BN    4
#define TN    32768
#define LCN   128
#define HOPN  256
#define HIDN  128
#define NLN   4
#define CONDN 512
#define CKN   384
#define KT    16     // K tile
#define SA    136    // smem row stride (conflict-free fragment loads)
#define TSZ   (KT * SA)

// ---------------- scratch ----------------
__device__ __align__(128) float g_kbuf[(size_t)BN * NLN * LCN * CKN * HIDN]; // [b][il][l][ck][cout]
__device__ __align__(128) float g_bbuf[BN * NLN * HIDN * LCN];
__device__ __align__(128) float g_h0[(size_t)BN * HIDN * TN];
__device__ __align__(128) float g_h1[(size_t)BN * HIDN * TN];
__device__ __align__(128) float g_wT[NLN * CKN * HIDN];

__device__ __forceinline__ float lrelu(float v, float s) { return v >= 0.f ? v : s * v; }

__device__ __forceinline__ void split_tf32(float x, unsigned& hi, unsigned& lo)
{
    unsigned u = __float_as_uint(x) & 0xFFFFE000u;
    hi = u;
    lo = __float_as_uint(x - __uint_as_float(u));
}

__device__ __forceinline__ void mma8(float* c, unsigned a0, unsigned a1, unsigned a2, unsigned a3,
                                     unsigned b0, unsigned b1)
{
    asm volatile(
        "mma.sync.aligned.m16n8k8.row.col.f32.tf32.tf32.f32 "
        "{%0,%1,%2,%3}, {%4,%5,%6,%7}, {%8,%9}, {%0,%1,%2,%3};\n"
        : "+f"(c[0]), "+f"(c[1]), "+f"(c[2]), "+f"(c[3])
        : "r"(a0), "r"(a1), "r"(a2), "r"(a3), "r"(b0), "r"(b1));
}

// 128x128 x K=16 tile with 3xTF32. As=[k][m], Bs=[k][n], stride SA.
__device__ __forceinline__ void tile_mma(const float* __restrict__ As,
                                         const float* __restrict__ Bs,
                                         int wm, int wn, int g, int tg,
                                         float (&acc)[4][4][4])
{
#pragma unroll
    for (int ks = 0; ks < 2; ks++) {
        const float* Ak0 = As + (ks * 8 + tg) * SA;
        const float* Ak4 = Ak0 + 4 * SA;
        const float* Bk0 = Bs + (ks * 8 + tg) * SA + wn * 32 + g;
        const float* Bk4 = Bk0 + 4 * SA;

        unsigned bhi[4][2], blo[4][2];
#pragma unroll
        for (int fn = 0; fn < 4; fn++) {
            split_tf32(Bk0[fn * 8], bhi[fn][0], blo[fn][0]);
            split_tf32(Bk4[fn * 8], bhi[fn][1], blo[fn][1]);
        }
#pragma unroll
        for (int fm = 0; fm < 4; fm++) {
            const int m0 = wm * 64 + fm * 16 + g;
            unsigned ahi[4], alo[4];
            split_tf32(Ak0[m0],     ahi[0], alo[0]);
            split_tf32(Ak0[m0 + 8], ahi[1], alo[1]);
            split_tf32(Ak4[m0],     ahi[2], alo[2]);
            split_tf32(Ak4[m0 + 8], ahi[3], alo[3]);
#pragma unroll
            for (int fn = 0; fn < 4; fn++) {
                mma8(acc[fm][fn], ahi[0], ahi[1], ahi[2], ahi[3], bhi[fn][0], bhi[fn][1]);
                mma8(acc[fm][fn], alo[0], alo[1], alo[2], alo[3], bhi[fn][0], bhi[fn][1]);
                mma8(acc[fm][fn], ahi[0], ahi[1], ahi[2], ahi[3], blo[fn][0], blo[fn][1]);
            }
        }
    }
}

// ============================================================================
// 1) Kernel predictor GEMM: m = l, n = cout, K = 512. double-buffered.
// ============================================================================
__global__ __launch_bounds__(256, 2) void kpred_gemm(const float* __restrict__ kw,
                                                     const float* __restrict__ kb,
                                                     const float* __restrict__ cond)
{
    __shared__ __align__(16) float As[2][TSZ];
    __shared__ __align__(16) float Bs[2][TSZ];
    __shared__ float bsm[128];

    const int b    = blockIdx.x;
    const int mblk = blockIdx.y;
    const int il   = mblk / CKN;
    const int ck   = mblk - il * CKN;
    const int cin  = ck / 3;
    const int kq   = ck - cin * 3;
    const int rbase = il * 49152 + cin * 384 + kq;

    const float* condb = cond + (size_t)b * CONDN * LCN;

    const int tid  = threadIdx.x;
    const int wid  = tid >> 5;
    const int lane = tid & 31;
    const int g    = lane >> 2;
    const int tg   = lane & 3;
    const int wm   = wid & 1;
    const int wn   = wid >> 1;

    if (tid < 128) bsm[tid] = kb[rbase + 3 * tid];

    // fixed per-thread load coords
    const int akk0 = tid >> 5,        alq0 = tid & 31;          // it=0
    const int akk1 = (tid + 256) >> 5, alq1 = tid & 31;         // it=1
    const int bm   = tid >> 2,        bq = tid & 3;             // it=0 (m 0..63)
    // it=1: m+64

    float4 ra[2], rb[2];
    const int NT = CONDN / KT;

    // prefetch tile 0
    ra[0] = *(const float4*)(condb + (size_t)akk0 * LCN + alq0 * 4);
    ra[1] = *(const float4*)(condb + (size_t)akk1 * LCN + alq1 * 4);
    rb[0] = *(const float4*)(kw + (size_t)(rbase + 3 * bm) * CONDN + bq * 4);
    rb[1] = *(const float4*)(kw + (size_t)(rbase + 3 * (bm + 64)) * CONDN + bq * 4);

    float acc[4][4][4];
#pragma unroll
    for (int i = 0; i < 4; i++)
#pragma unroll
        for (int j = 0; j < 4; j++)
#pragma unroll
            for (int q = 0; q < 4; q++) acc[i][j][q] = 0.f;

    // store tile 0
    {
        float* A0 = As[0];
        *(float4*)&A0[akk0 * SA + alq0 * 4] = ra[0];
        *(float4*)&A0[akk1 * SA + alq1 * 4] = ra[1];
        float* B0 = Bs[0];
        B0[(bq*4+0)*SA + bm] = rb[0].x; B0[(bq*4+1)*SA + bm] = rb[0].y;
        B0[(bq*4+2)*SA + bm] = rb[0].z; B0[(bq*4+3)*SA + bm] = rb[0].w;
        B0[(bq*4+0)*SA + bm+64] = rb[1].x; B0[(bq*4+1)*SA + bm+64] = rb[1].y;
        B0[(bq*4+2)*SA + bm+64] = rb[1].z; B0[(bq*4+3)*SA + bm+64] = rb[1].w;
    }
    __syncthreads();

    for (int t = 0; t < NT; t++) {
        const int k1 = (t + 1) * KT;
        if (t + 1 < NT) {
            ra[0] = *(const float4*)(condb + (size_t)(k1 + akk0) * LCN + alq0 * 4);
            ra[1] = *(const float4*)(condb + (size_t)(k1 + akk1) * LCN + alq1 * 4);
            rb[0] = *(const float4*)(kw + (size_t)(rbase + 3 * bm) * CONDN + k1 + bq * 4);
            rb[1] = *(const float4*)(kw + (size_t)(rbase + 3 * (bm + 64)) * CONDN + k1 + bq * 4);
        }
        tile_mma(As[t & 1], Bs[t & 1], wm, wn, g, tg, acc);
        if (t + 1 < NT) {
            float* A1 = As[(t + 1) & 1];
            *(float4*)&A1[akk0 * SA + alq0 * 4] = ra[0];
            *(float4*)&A1[akk1 * SA + alq1 * 4] = ra[1];
            float* B1 = Bs[(t + 1) & 1];
            B1[(bq*4+0)*SA + bm] = rb[0].x; B1[(bq*4+1)*SA + bm] = rb[0].y;
            B1[(bq*4+2)*SA + bm] = rb[0].z; B1[(bq*4+3)*SA + bm] = rb[0].w;
            B1[(bq*4+0)*SA + bm+64] = rb[1].x; B1[(bq*4+1)*SA + bm+64] = rb[1].y;
            B1[(bq*4+2)*SA + bm+64] = rb[1].z; B1[(bq*4+3)*SA + bm+64] = rb[1].w;
            __syncthreads();
        }
    }

    const size_t base = ((size_t)(b * NLN + il) * LCN) * ((size_t)CKN * HIDN) + (size_t)ck * HIDN;
#pragma unroll
    for (int fm = 0; fm < 4; fm++) {
        const int l0 = wm * 64 + fm * 16 + g;
        float* row0 = g_kbuf + base + (size_t)l0 * (CKN * HIDN);
        float* row1 = row0 + (size_t)8 * (CKN * HIDN);
#pragma unroll
        for (int fn = 0; fn < 4; fn++) {
            const int n0 = wn * 32 + fn * 8 + 2 * tg;
            float b0 = bsm[n0], b1 = bsm[n0 + 1];
            float2 v0, v1;
            v0.x = acc[fm][fn][0] + b0; v0.y = acc[fm][fn][1] + b1;
            v1.x = acc[fm][fn][2] + b0; v1.y = acc[fm][fn][3] + b1;
            *(float2*)(row0 + n0) = v0;
            *(float2*)(row1 + n0) = v1;
        }
    }
}

// ============================================================================
// 2) Bias predictor
// ============================================================================
__global__ void bias_pred(const float* __restrict__ bw, const float* __restrict__ bb,
                          const float* __restrict__ cond)
{
    __shared__ float ws[CONDN];
    const int r = blockIdx.x, b = blockIdx.y;
    const int l = threadIdx.x;
    for (int c = l; c < CONDN; c += 128) ws[c] = bw[(size_t)r * CONDN + c];
    __syncthreads();
    const float* condb = cond + (size_t)b * CONDN * LCN + l;
    float acc = bb[r];
#pragma unroll 8
    for (int c = 0; c < CONDN; c++) acc += ws[c] * condb[(size_t)c * LCN];
    g_bbuf[((size_t)b * (NLN * HIDN) + r) * LCN + l] = acc;
}

// ============================================================================
// 3) transpose block_w
// ============================================================================
__global__ void transpose_w(const float* __restrict__ bw)
{
    int idx = blockIdx.x * blockDim.x + threadIdx.x;
    if (idx >= NLN * CKN * HIDN) return;
    int il = idx / (CKN * HIDN);
    int rem = idx - il * (CKN * HIDN);
    int ck = rem >> 7, o = rem & 127;
    int cin = ck / 3, k = ck - cin * 3;
    g_wT[idx] = bw[((size_t)(il * HIDN + o) * HIDN + cin) * 3 + k];
}

// ============================================================================
// 4) preconv
// ============================================================================
__global__ void preconv(const float* __restrict__ x, const float* __restrict__ pw,
                        const float* __restrict__ pb)
{
    int idx = blockIdx.x * blockDim.x + threadIdx.x;
    const int T4 = TN / 4;
    int t4 = idx % T4;
    int ch = (idx / T4) & (HIDN - 1);
    int b  = idx / (T4 * HIDN);
    float w = pw[ch], bi = pb[ch];
    float4 xv = *(const float4*)(x + (size_t)b * TN + (size_t)t4 * 4);
    float4 o;
    o.x = lrelu(w * xv.x + bi, 0.2f);
    o.y = lrelu(w * xv.y + bi, 0.2f);
    o.z = lrelu(w * xv.z + bi, 0.2f);
    o.w = lrelu(w * xv.w + bi, 0.2f);
    *(float4*)(g_h0 + ((size_t)(b * HIDN + ch)) * TN + (size_t)t4 * 4) = o;
}

// ============================================================================
// shared body for LVC / dilconv: A = W[ck][o], B = gathered H. double-buffered.
// gather: t = t0 + s + (k-1)*d   (lvc: d=1)
// ============================================================================
template <bool IS_LVC>
__device__ __forceinline__ void conv_gemm_body(const float* __restrict__ Wb,
                                               const float* __restrict__ hb,
                                               float* __restrict__ outp,   // [o][t] base + t0
                                               const float* __restrict__ biasv, // bsm[128]
                                               int t0, int d)
{
    __shared__ __align__(16) float As[2][TSZ];
    __shared__ __align__(16) float Bs[2][TSZ];

    const int tid  = threadIdx.x;
    const int wid  = tid >> 5;
    const int lane = tid & 31;
    const int g    = lane >> 2;
    const int tg   = lane & 3;
    const int wm   = wid & 1;
    const int wn   = wid >> 1;

    // A load coords (2 x float4)
    const int akk0 = tid >> 5,         aoq = (tid & 31) * 4;
    const int akk1 = (tid + 256) >> 5;
    // B gather coords: 8 elements, kk = (tid+it*256)>>7, s = tid&127
    const int bs = tid & 127;

    float4 ra[2];
    float rbv[8];
    const int NT = CKN / KT;

    auto ldgB = [&](int c0, float* dst) {
#pragma unroll
        for (int it = 0; it < 8; it++) {
            int kk = ((tid + it * 256) >> 7);
            int ck2 = c0 + kk;
            int cin = ck2 / 3, k = ck2 - cin * 3;
            int t = t0 + bs + (k - 1) * d;
            dst[it] = (t >= 0 && t < TN) ? hb[(size_t)cin * TN + t] : 0.f;
        }
    };

    ra[0] = *(const float4*)(Wb + (size_t)akk0 * HIDN + aoq);
    ra[1] = *(const float4*)(Wb + (size_t)akk1 * HIDN + aoq);
    ldgB(0, rbv);

    float acc[4][4][4];
#pragma unroll
    for (int i = 0; i < 4; i++)
#pragma unroll
        for (int j = 0; j < 4; j++)
#pragma unroll
            for (int q = 0; q < 4; q++) acc[i][j][q] = 0.f;

    {
        float* A0 = As[0];
        *(float4*)&A0[akk0 * SA + aoq] = ra[0];
        *(float4*)&A0[akk1 * SA + aoq] = ra[1];
        float* B0 = Bs[0];
#pragma unroll
        for (int it = 0; it < 8; it++) {
            int kk = ((tid + it * 256) >> 7);
            B0[kk * SA + bs] = rbv[it];
        }
    }
    __syncthreads();

    for (int t = 0; t < NT; t++) {
        const int c1 = (t + 1) * KT;
        if (t + 1 < NT) {
            ra[0] = *(const float4*)(Wb + (size_t)(c1 + akk0) * HIDN + aoq);
            ra[1] = *(const float4*)(Wb + (size_t)(c1 + akk1) * HIDN + aoq);
            ldgB(c1, rbv);
        }
        tile_mma(As[t & 1], Bs[t & 1], wm, wn, g, tg, acc);
        if (t + 1 < NT) {
            float* A1 = As[(t + 1) & 1];
            *(float4*)&A1[akk0 * SA + aoq] = ra[0];
            *(float4*)&A1[akk1 * SA + aoq] = ra[1];
            float* B1 = Bs[(t + 1) & 1];
#pragma unroll
            for (int it = 0; it < 8; it++) {
                int kk = ((tid + it * 256) >> 7);
                B1[kk * SA + bs] = rbv[it];
            }
            __syncthreads();
        }
    }

#pragma unroll
    for (int fm = 0; fm < 4; fm++) {
        const int o0 = wm * 64 + fm * 16 + g;
        float b0 = biasv[o0], b1 = biasv[o0 + 8];
        float* row0 = outp + (size_t)o0 * TN;
        float* row1 = row0 + (size_t)8 * TN;
#pragma unroll
        for (int fn = 0; fn < 4; fn++) {
            const int n0 = wn * 32 + fn * 8 + 2 * tg;
            float2 v0, v1;
            v0.x = lrelu(acc[fm][fn][0] + b0, 3.f);
            v0.y = lrelu(acc[fm][fn][1] + b0, 3.f);
            v1.x = lrelu(acc[fm][fn][2] + b1, 3.f);
            v1.y = lrelu(acc[fm][fn][3] + b1, 3.f);
            *(float2*)(row0 + n0) = v0;
            *(float2*)(row1 + n0) = v1;
        }
    }
}

// 5) LVC: g_h0 -> g_h1
__global__ __launch_bounds__(256, 2) void lvc_gemm(int il)
{
    __shared__ float bsm[128];
    const int sh = blockIdx.x;
    const int l  = blockIdx.y;
    const int b  = blockIdx.z;
    const int t0 = l * HOPN + sh * 128;

    if (threadIdx.x < 128)
        bsm[threadIdx.x] = g_bbuf[((size_t)b * (NLN * HIDN) + il * HIDN + threadIdx.x) * LCN + l];
    __syncthreads();

    const float* Wb = g_kbuf + ((size_t)(b * NLN + il) * LCN + l) * ((size_t)CKN * HIDN);
    const float* hb = g_h0 + (size_t)b * HIDN * TN;
    float* outp = g_h1 + (size_t)b * HIDN * TN + t0;
    conv_gemm_body<true>(Wb, hb, outp, bsm, t0, 1);
}

// 6) dilated conv: g_h1 -> g_h0
__global__ __launch_bounds__(256, 2) void dil_gemm(int il, int d, const float* __restrict__ blockb)
{
    __shared__ float bsm[128];
    const int t0 = blockIdx.x * 128;
    const int b  = blockIdx.y;
    if (threadIdx.x < 128) bsm[threadIdx.x] = blockb[il * HIDN + threadIdx.x];
    __syncthreads();

    const float* Wb = g_wT + (size_t)il * CKN * HIDN;
    const float* hb = g_h1 + (size_t)b * HIDN * TN;
    float* outp = g_h0 + (size_t)b * HIDN * TN + t0;
    conv_gemm_body<false>(Wb, hb, outp, bsm, t0, d);
}

// ============================================================================
// 7) postconv
// ============================================================================
__global__ void postconv(const float* __restrict__ pw, const float* __restrict__ pb,
                         float* __restrict__ out)
{
    __shared__ float ws[HIDN];
    const int t = blockIdx.x * 256 + threadIdx.x;
    const int b = blockIdx.y;
    if (threadIdx.x < HIDN) ws[threadIdx.x] = pw[threadIdx.x];
    __syncthreads();
    float acc = pb[0];
    const float* hb = g_h0 + (size_t)b * HIDN * TN + t;
#pragma unroll 8
    for (int o = 0; o < HIDN; o++) acc += ws[o] * hb[(size_t)o * TN];
    out[(size_t)b * TN + t] = acc;
}

// ============================================================================
extern "C" void kernel_launch(void* const* d_in, const int* in_sizes, int n_in,
                              void* d_out, int out_size)
{
    const float* x        = (const float*)d_in[0];
    const float* c        = (const float*)d_in[1];
    const float* kernel_w = (const float*)d_in[2];
    const float* kernel_b = (const float*)d_in[3];
    const float* biasp_w  = (const float*)d_in[4];
    const float* biasp_b  = (const float*)d_in[5];
    const float* pre_w    = (const float*)d_in[6];
    const float* pre_b    = (const float*)d_in[7];
    const float* block_w  = (const float*)d_in[8];
    const float* block_b  = (const float*)d_in[9];
    const float* post_w   = (const float*)d_in[10];
    const float* post_b   = (const float*)d_in[11];
    float* out = (float*)d_out;

    kpred_gemm<<<dim3(BN, (NLN * CKN)), 256>>>(kernel_w, kernel_b, c);
    bias_pred<<<dim3(NLN * HIDN, BN), 128>>>(biasp_w, biasp_b, c);
    transpose_w<<<(NLN * CKN * HIDN + 255) / 256, 256>>>(block_w);
    preconv<<<(BN * HIDN * TN / 4) / 256, 256>>>(x, pre_w, pre_b);

    const int dils[NLN] = {1, 3, 9, 27};
    for (int i = 0; i < NLN; i++) {
        lvc_gemm<<<dim3(2, LCN, BN), 256>>>(i);
        dil_gemm<<<dim3(TN / 128, BN), 256>>>(i, dils[i], block_b);
    }
    postconv<<<dim3(TN / 256, BN), 256>>>(post_w, post_b, out);
}

// round 9
// speedup vs baseline: 1.6061x; 1.0032x over previous
#include <cuda_runtime.h>

// ---------------- problem constants ----------------
#define BN    4
#define TN    32768
#define LCN   128
#define HOPN  256
#define HIDN  128
#define NLN   4
#define CONDN 512
#define CKN   384
#define KT    16     // K tile
#define SA    136    // smem row stride (conflict-free fragment loads)
#define TSZ   (KT * SA)

// ---------------- scratch ----------------
__device__ __align__(128) float g_kbuf[(size_t)BN * NLN * LCN * CKN * HIDN]; // [b][il][l][ck][cout]
__device__ __align__(128) float g_bbuf[BN * NLN * HIDN * LCN];
__device__ __align__(128) float g_h0[(size_t)BN * HIDN * TN];
__device__ __align__(128) float g_h1[(size_t)BN * HIDN * TN];
__device__ __align__(128) float g_wT[NLN * CKN * HIDN];

__device__ __forceinline__ float lrelu(float v, float s) { return v >= 0.f ? v : s * v; }

__device__ __forceinline__ void split_tf32(float x, unsigned& hi, unsigned& lo)
{
    unsigned u = __float_as_uint(x) & 0xFFFFE000u;
    hi = u;
    lo = __float_as_uint(x - __uint_as_float(u));
}

__device__ __forceinline__ void mma8(float* c, unsigned a0, unsigned a1, unsigned a2, unsigned a3,
                                     unsigned b0, unsigned b1)
{
    asm volatile(
        "mma.sync.aligned.m16n8k8.row.col.f32.tf32.tf32.f32 "
        "{%0,%1,%2,%3}, {%4,%5,%6,%7}, {%8,%9}, {%0,%1,%2,%3};\n"
        : "+f"(c[0]), "+f"(c[1]), "+f"(c[2]), "+f"(c[3])
        : "r"(a0), "r"(a1), "r"(a2), "r"(a3), "r"(b0), "r"(b1));
}

// 128x128 x K=16 tile with 3xTF32. As=[k][m], Bs=[k][n], stride SA.
__device__ __forceinline__ void tile_mma(const float* __restrict__ As,
                                         const float* __restrict__ Bs,
                                         int wm, int wn, int g, int tg,
                                         float (&acc)[4][4][4])
{
#pragma unroll
    for (int ks = 0; ks < 2; ks++) {
        const float* Ak0 = As + (ks * 8 + tg) * SA;
        const float* Ak4 = Ak0 + 4 * SA;
        const float* Bk0 = Bs + (ks * 8 + tg) * SA + wn * 32 + g;
        const float* Bk4 = Bk0 + 4 * SA;

        unsigned bhi[4][2], blo[4][2];
#pragma unroll
        for (int fn = 0; fn < 4; fn++) {
            split_tf32(Bk0[fn * 8], bhi[fn][0], blo[fn][0]);
            split_tf32(Bk4[fn * 8], bhi[fn][1], blo[fn][1]);
        }
#pragma unroll
        for (int fm = 0; fm < 4; fm++) {
            const int m0 = wm * 64 + fm * 16 + g;
            unsigned ahi[4], alo[4];
            split_tf32(Ak0[m0],     ahi[0], alo[0]);
            split_tf32(Ak0[m0 + 8], ahi[1], alo[1]);
            split_tf32(Ak4[m0],     ahi[2], alo[2]);
            split_tf32(Ak4[m0 + 8], ahi[3], alo[3]);
#pragma unroll
            for (int fn = 0; fn < 4; fn++) {
                mma8(acc[fm][fn], ahi[0], ahi[1], ahi[2], ahi[3], bhi[fn][0], bhi[fn][1]);
                mma8(acc[fm][fn], alo[0], alo[1], alo[2], alo[3], bhi[fn][0], bhi[fn][1]);
                mma8(acc[fm][fn], ahi[0], ahi[1], ahi[2], ahi[3], blo[fn][0], blo[fn][1]);
            }
        }
    }
}

// ============================================================================
// 1) Kernel predictor GEMM: m = l, n = cout, K = 512. double-buffered.
// ============================================================================
__global__ __launch_bounds__(256, 2) void kpred_gemm(const float* __restrict__ kw,
                                                     const float* __restrict__ kb,
                                                     const float* __restrict__ cond)
{
    __shared__ __align__(16) float As[2][TSZ];
    __shared__ __align__(16) float Bs[2][TSZ];
    __shared__ float bsm[128];

    const int b    = blockIdx.x;
    const int mblk = blockIdx.y;
    const int il   = mblk / CKN;
    const int ck   = mblk - il * CKN;
    const int cin  = ck / 3;
    const int kq   = ck - cin * 3;
    const int rbase = il * 49152 + cin * 384 + kq;

    const float* condb = cond + (size_t)b * CONDN * LCN;

    const int tid  = threadIdx.x;
    const int wid  = tid >> 5;
    const int lane = tid & 31;
    const int g    = lane >> 2;
    const int tg   = lane & 3;
    const int wm   = wid & 1;
    const int wn   = wid >> 1;

    if (tid < 128) bsm[tid] = kb[rbase + 3 * tid];

    // fixed per-thread load coords
    const int akk0 = tid >> 5,        alq0 = tid & 31;          // it=0
    const int akk1 = (tid + 256) >> 5, alq1 = tid & 31;         // it=1
    const int bm   = tid >> 2,        bq = tid & 3;             // it=0 (m 0..63)
    // it=1: m+64

    float4 ra[2], rb[2];
    const int NT = CONDN / KT;

    // prefetch tile 0
    ra[0] = *(const float4*)(condb + (size_t)akk0 * LCN + alq0 * 4);
    ra[1] = *(const float4*)(condb + (size_t)akk1 * LCN + alq1 * 4);
    rb[0] = *(const float4*)(kw + (size_t)(rbase + 3 * bm) * CONDN + bq * 4);
    rb[1] = *(const float4*)(kw + (size_t)(rbase + 3 * (bm + 64)) * CONDN + bq * 4);

    float acc[4][4][4];
#pragma unroll
    for (int i = 0; i < 4; i++)
#pragma unroll
        for (int j = 0; j < 4; j++)
#pragma unroll
            for (int q = 0; q < 4; q++) acc[i][j][q] = 0.f;

    // store tile 0
    {
        float* A0 = As[0];
        *(float4*)&A0[akk0 * SA + alq0 * 4] = ra[0];
        *(float4*)&A0[akk1 * SA + alq1 * 4] = ra[1];
        float* B0 = Bs[0];
        B0[(bq*4+0)*SA + bm] = rb[0].x; B0[(bq*4+1)*SA + bm] = rb[0].y;
        B0[(bq*4+2)*SA + bm] = rb[0].z; B0[(bq*4+3)*SA + bm] = rb[0].w;
        B0[(bq*4+0)*SA + bm+64] = rb[1].x; B0[(bq*4+1)*SA + bm+64] = rb[1].y;
        B0[(bq*4+2)*SA + bm+64] = rb[1].z; B0[(bq*4+3)*SA + bm+64] = rb[1].w;
    }
    __syncthreads();

    for (int t = 0; t < NT; t++) {
        const int k1 = (t + 1) * KT;
        if (t + 1 < NT) {
            ra[0] = *(const float4*)(condb + (size_t)(k1 + akk0) * LCN + alq0 * 4);
            ra[1] = *(const float4*)(condb + (size_t)(k1 + akk1) * LCN + alq1 * 4);
            rb[0] = *(const float4*)(kw + (size_t)(rbase + 3 * bm) * CONDN + k1 + bq * 4);
            rb[1] = *(const float4*)(kw + (size_t)(rbase + 3 * (bm + 64)) * CONDN + k1 + bq * 4);
        }
        tile_mma(As[t & 1], Bs[t & 1], wm, wn, g, tg, acc);
        if (t + 1 < NT) {
            float* A1 = As[(t + 1) & 1];
            *(float4*)&A1[akk0 * SA + alq0 * 4] = ra[0];
            *(float4*)&A1[akk1 * SA + alq1 * 4] = ra[1];
            float* B1 = Bs[(t + 1) & 1];
            B1[(bq*4+0)*SA + bm] = rb[0].x; B1[(bq*4+1)*SA + bm] = rb[0].y;
            B1[(bq*4+2)*SA + bm] = rb[0].z; B1[(bq*4+3)*SA + bm] = rb[0].w;
            B1[(bq*4+0)*SA + bm+64] = rb[1].x; B1[(bq*4+1)*SA + bm+64] = rb[1].y;
            B1[(bq*4+2)*SA + bm+64] = rb[1].z; B1[(bq*4+3)*SA + bm+64] = rb[1].w;
            __syncthreads();
        }
    }

    const size_t base = ((size_t)(b * NLN + il) * LCN) * ((size_t)CKN * HIDN) + (size_t)ck * HIDN;
#pragma unroll
    for (int fm = 0; fm < 4; fm++) {
        const int l0 = wm * 64 + fm * 16 + g;
        float* row0 = g_kbuf + base + (size_t)l0 * (CKN * HIDN);
        float* row1 = row0 + (size_t)8 * (CKN * HIDN);
#pragma unroll
        for (int fn = 0; fn < 4; fn++) {
            const int n0 = wn * 32 + fn * 8 + 2 * tg;
            float b0 = bsm[n0], b1 = bsm[n0 + 1];
            float2 v0, v1;
            v0.x = acc[fm][fn][0] + b0; v0.y = acc[fm][fn][1] + b1;
            v1.x = acc[fm][fn][2] + b0; v1.y = acc[fm][fn][3] + b1;
            *(float2*)(row0 + n0) = v0;
            *(float2*)(row1 + n0) = v1;
        }
    }
}

// ============================================================================
// 2) Bias predictor
// ============================================================================
__global__ void bias_pred(const float* __restrict__ bw, const float* __restrict__ bb,
                          const float* __restrict__ cond)
{
    __shared__ float ws[CONDN];
    const int r = blockIdx.x, b = blockIdx.y;
    const int l = threadIdx.x;
    for (int c = l; c < CONDN; c += 128) ws[c] = bw[(size_t)r * CONDN + c];
    __syncthreads();
    const float* condb = cond + (size_t)b * CONDN * LCN + l;
    float acc = bb[r];
#pragma unroll 8
    for (int c = 0; c < CONDN; c++) acc += ws[c] * condb[(size_t)c * LCN];
    g_bbuf[((size_t)b * (NLN * HIDN) + r) * LCN + l] = acc;
}

// ============================================================================
// 3) transpose block_w
// ============================================================================
__global__ void transpose_w(const float* __restrict__ bw)
{
    int idx = blockIdx.x * blockDim.x + threadIdx.x;
    if (idx >= NLN * CKN * HIDN) return;
    int il = idx / (CKN * HIDN);
    int rem = idx - il * (CKN * HIDN);
    int ck = rem >> 7, o = rem & 127;
    int cin = ck / 3, k = ck - cin * 3;
    g_wT[idx] = bw[((size_t)(il * HIDN + o) * HIDN + cin) * 3 + k];
}

// ============================================================================
// 4) preconv
// ============================================================================
__global__ void preconv(const float* __restrict__ x, const float* __restrict__ pw,
                        const float* __restrict__ pb)
{
    int idx = blockIdx.x * blockDim.x + threadIdx.x;
    const int T4 = TN / 4;
    int t4 = idx % T4;
    int ch = (idx / T4) & (HIDN - 1);
    int b  = idx / (T4 * HIDN);
    float w = pw[ch], bi = pb[ch];
    float4 xv = *(const float4*)(x + (size_t)b * TN + (size_t)t4 * 4);
    float4 o;
    o.x = lrelu(w * xv.x + bi, 0.2f);
    o.y = lrelu(w * xv.y + bi, 0.2f);
    o.z = lrelu(w * xv.z + bi, 0.2f);
    o.w = lrelu(w * xv.w + bi, 0.2f);
    *(float4*)(g_h0 + ((size_t)(b * HIDN + ch)) * TN + (size_t)t4 * 4) = o;
}

// ============================================================================
// shared body for LVC / dilconv: A = W[ck][o], B = gathered H. double-buffered.
// gather: t = t0 + s + (k-1)*d   (lvc: d=1)
// ============================================================================
template <bool IS_LVC>
__device__ __forceinline__ void conv_gemm_body(const float* __restrict__ Wb,
                                               const float* __restrict__ hb,
                                               float* __restrict__ outp,   // [o][t] base + t0
                                               const float* __restrict__ biasv, // bsm[128]
                                               int t0, int d)
{
    __shared__ __align__(16) float As[2][TSZ];
    __shared__ __align__(16) float Bs[2][TSZ];

    const int tid  = threadIdx.x;
    const int wid  = tid >> 5;
    const int lane = tid & 31;
    const int g    = lane >> 2;
    const int tg   = lane & 3;
    const int wm   = wid & 1;
    const int wn   = wid >> 1;

    // A load coords (2 x float4)
    const int akk0 = tid >> 5,         aoq = (tid & 31) * 4;
    const int akk1 = (tid + 256) >> 5;
    // B gather coords: 8 elements, kk = (tid+it*256)>>7, s = tid&127
    const int bs = tid & 127;

    float4 ra[2];
    float rbv[8];
    const int NT = CKN / KT;

    auto ldgB = [&](int c0, float* dst) {
#pragma unroll
        for (int it = 0; it < 8; it++) {
            int kk = ((tid + it * 256) >> 7);
            int ck2 = c0 + kk;
            int cin = ck2 / 3, k = ck2 - cin * 3;
            int t = t0 + bs + (k - 1) * d;
            dst[it] = (t >= 0 && t < TN) ? hb[(size_t)cin * TN + t] : 0.f;
        }
    };

    ra[0] = *(const float4*)(Wb + (size_t)akk0 * HIDN + aoq);
    ra[1] = *(const float4*)(Wb + (size_t)akk1 * HIDN + aoq);
    ldgB(0, rbv);

    float acc[4][4][4];
#pragma unroll
    for (int i = 0; i < 4; i++)
#pragma unroll
        for (int j = 0; j < 4; j++)
#pragma unroll
            for (int q = 0; q < 4; q++) acc[i][j][q] = 0.f;

    {
        float* A0 = As[0];
        *(float4*)&A0[akk0 * SA + aoq] = ra[0];
        *(float4*)&A0[akk1 * SA + aoq] = ra[1];
        float* B0 = Bs[0];
#pragma unroll
        for (int it = 0; it < 8; it++) {
            int kk = ((tid + it * 256) >> 7);
            B0[kk * SA + bs] = rbv[it];
        }
    }
    __syncthreads();

    for (int t = 0; t < NT; t++) {
        const int c1 = (t + 1) * KT;
        if (t + 1 < NT) {
            ra[0] = *(const float4*)(Wb + (size_t)(c1 + akk0) * HIDN + aoq);
            ra[1] = *(const float4*)(Wb + (size_t)(c1 + akk1) * HIDN + aoq);
            ldgB(c1, rbv);
        }
        tile_mma(As[t & 1], Bs[t & 1], wm, wn, g, tg, acc);
        if (t + 1 < NT) {
            float* A1 = As[(t + 1) & 1];
            *(float4*)&A1[akk0 * SA + aoq] = ra[0];
            *(float4*)&A1[akk1 * SA + aoq] = ra[1];
            float* B1 = Bs[(t + 1) & 1];
#pragma unroll
            for (int it = 0; it < 8; it++) {
                int kk = ((tid + it * 256) >> 7);
                B1[kk * SA + bs] = rbv[it];
            }
            __syncthreads();
        }
    }

#pragma unroll
    for (int fm = 0; fm < 4; fm++) {
        const int o0 = wm * 64 + fm * 16 + g;
        float b0 = biasv[o0], b1 = biasv[o0 + 8];
        float* row0 = outp + (size_t)o0 * TN;
        float* row1 = row0 + (size_t)8 * TN;
#pragma unroll
        for (int fn = 0; fn < 4; fn++) {
            const int n0 = wn * 32 + fn * 8 + 2 * tg;
            float2 v0, v1;
            v0.x = lrelu(acc[fm][fn][0] + b0, 3.f);
            v0.y = lrelu(acc[fm][fn][1] + b0, 3.f);
            v1.x = lrelu(acc[fm][fn][2] + b1, 3.f);
            v1.y = lrelu(acc[fm][fn][3] + b1, 3.f);
            *(float2*)(row0 + n0) = v0;
            *(float2*)(row1 + n0) = v1;
        }
    }
}

// 5) LVC: g_h0 -> g_h1
__global__ __launch_bounds__(256, 2) void lvc_gemm(int il)
{
    __shared__ float bsm[128];
    const int sh = blockIdx.x;
    const int l  = blockIdx.y;
    const int b  = blockIdx.z;
    const int t0 = l * HOPN + sh * 128;

    if (threadIdx.x < 128)
        bsm[threadIdx.x] = g_bbuf[((size_t)b * (NLN * HIDN) + il * HIDN + threadIdx.x) * LCN + l];
    __syncthreads();

    const float* Wb = g_kbuf + ((size_t)(b * NLN + il) * LCN + l) * ((size_t)CKN * HIDN);
    const float* hb = g_h0 + (size_t)b * HIDN * TN;
    float* outp = g_h1 + (size_t)b * HIDN * TN + t0;
    conv_gemm_body<true>(Wb, hb, outp, bsm, t0, 1);
}

// 6) dilated conv: g_h1 -> g_h0
__global__ __launch_bounds__(256, 2) void dil_gemm(int il, int d, const float* __restrict__ blockb)
{
    __shared__ float bsm[128];
    const int t0 = blockIdx.x * 128;
    const int b  = blockIdx.y;
    if (threadIdx.x < 128) bsm[threadIdx.x] = blockb[il * HIDN + threadIdx.x];
    __syncthreads();

    const float* Wb = g_wT + (size_t)il * CKN * HIDN;
    const float* hb = g_h1 + (size_t)b * HIDN * TN;
    float* outp = g_h0 + (size_t)b * HIDN * TN + t0;
    conv_gemm_body<false>(Wb, hb, outp, bsm, t0, d);
}

// ============================================================================
// 7) postconv
// ============================================================================
__global__ void postconv(const float* __restrict__ pw, const float* __restrict__ pb,
                         float* __restrict__ out)
{
    __shared__ float ws[HIDN];
    const int t = blockIdx.x * 256 + threadIdx.x;
    const int b = blockIdx.y;
    if (threadIdx.x < HIDN) ws[threadIdx.x] = pw[threadIdx.x];
    __syncthreads();
    float acc = pb[0];
    const float* hb = g_h0 + (size_t)b * HIDN * TN + t;
#pragma unroll 8
    for (int o = 0; o < HIDN; o++) acc += ws[o] * hb[(size_t)o * TN];
    out[(size_t)b * TN + t] = acc;
}

// ============================================================================
extern "C" void kernel_launch(void* const* d_in, const int* in_sizes, int n_in,
                              void* d_out, int out_size)
{
    const float* x        = (const float*)d_in[0];
    const float* c        = (const float*)d_in[1];
    const float* kernel_w = (const float*)d_in[2];
    const float* kernel_b = (const float*)d_in[3];
    const float* biasp_w  = (const float*)d_in[4];
    const float* biasp_b  = (const float*)d_in[5];
    const float* pre_w    = (const float*)d_in[6];
    const float* pre_b    = (const float*)d_in[7];
    const float* block_w  = (const float*)d_in[8];
    const float* block_b  = (const float*)d_in[9];
    const float* post_w   = (const float*)d_in[10];
    const float* post_b   = (const float*)d_in[11];
    float* out = (float*)d_out;

    kpred_gemm<<<dim3(BN, (NLN * CKN)), 256>>>(kernel_w, kernel_b, c);
    bias_pred<<<dim3(NLN * HIDN, BN), 128>>>(biasp_w, biasp_b, c);
    transpose_w<<<(NLN * CKN * HIDN + 255) / 256, 256>>>(block_w);
    preconv<<<(BN * HIDN * TN / 4) / 256, 256>>>(x, pre_w, pre_b);

    const int dils[NLN] = {1, 3, 9, 27};
    for (int i = 0; i < NLN; i++) {
        lvc_gemm<<<dim3(2, LCN, BN), 256>>>(i);
        dil_gemm<<<dim3(TN / 128, BN), 256>>>(i, dils[i], block_b);
    }
    postconv<<<dim3(TN / 256, BN), 256>>>(post_w, post_b, out);
}

// round 12
// speedup vs baseline: 2.0275x; 1.2624x over previous
#include <cuda_runtime.h>
#include <cuda_fp16.h>
#include <cstdint>

// ---------------- problem constants ----------------
#define BN    4
#define TN    32768
#define LCN   128
#define HOPN  256
#define HIDN  128
#define NLN   4
#define CONDN 512
#define CKN   384
#define TK    16       // K per staged tile (one m16n8k16 step)
#define SB    132      // smem row stride in half2 units (bank-conflict-free)
#define TILE  (8 * SB) // one operand tile: 8 k-pair rows x 132

// ---------------- scratch ----------------
__device__ __align__(128) float g_kbuf[(size_t)BN * NLN * LCN * CKN * HIDN]; // [b][il][l][ck][cout]
__device__ __align__(128) float g_bbuf[BN * NLN * HIDN * LCN];
__device__ __align__(128) float g_h0[(size_t)BN * HIDN * TN];
__device__ __align__(128) float g_h1[(size_t)BN * HIDN * TN];

__device__ __forceinline__ float lrelu(float v, float s) { return v >= 0.f ? v : s * v; }

// fp32 -> fp16 hi + fp16 lo (pairwise, packed half2 as u32)
__device__ __forceinline__ void split_pair(float x0, float x1, uint32_t& hi, uint32_t& lo)
{
    __half h0 = __float2half_rn(x0), h1 = __float2half_rn(x1);
    __half l0 = __float2half_rn(x0 - __half2float(h0));
    __half l1 = __float2half_rn(x1 - __half2float(h1));
    __half2 hh = __halves2half2(h0, h1);
    __half2 ll = __halves2half2(l0, l1);
    hi = *(uint32_t*)&hh;
    lo = *(uint32_t*)&ll;
}

__device__ __forceinline__ void mma16(float* c, uint32_t a0, uint32_t a1, uint32_t a2, uint32_t a3,
                                      uint32_t b0, uint32_t b1)
{
    asm volatile(
        "mma.sync.aligned.m16n8k16.row.col.f32.f16.f16.f32 "
        "{%0,%1,%2,%3}, {%4,%5,%6,%7}, {%8,%9}, {%0,%1,%2,%3};\n"
        : "+f"(c[0]), "+f"(c[1]), "+f"(c[2]), "+f"(c[3])
        : "r"(a0), "r"(a1), "r"(a2), "r"(a3), "r"(b0), "r"(b1));
}

// 128x128 x K=16 tile, 3-product fp16 split. Tiles are u32(half2) [kp][m]/[kp][n], stride SB.
__device__ __forceinline__ void tile_mma(const uint32_t* __restrict__ Ah,
                                         const uint32_t* __restrict__ Al,
                                         const uint32_t* __restrict__ Bh,
                                         const uint32_t* __restrict__ Bl,
                                         int wm, int wn, int g, int tg,
                                         float (&acc)[4][4][4])
{
    uint32_t bh[4][2], bl[4][2];
#pragma unroll
    for (int fn = 0; fn < 4; fn++) {
        const int n = wn * 32 + fn * 8 + g;
        bh[fn][0] = Bh[tg * SB + n];       bh[fn][1] = Bh[(tg + 4) * SB + n];
        bl[fn][0] = Bl[tg * SB + n];       bl[fn][1] = Bl[(tg + 4) * SB + n];
    }
#pragma unroll
    for (int fm = 0; fm < 4; fm++) {
        const int m = wm * 64 + fm * 16 + g;
        uint32_t ah[4], al[4];
        ah[0] = Ah[tg * SB + m];       ah[1] = Ah[tg * SB + m + 8];
        ah[2] = Ah[(tg + 4) * SB + m]; ah[3] = Ah[(tg + 4) * SB + m + 8];
        al[0] = Al[tg * SB + m];       al[1] = Al[tg * SB + m + 8];
        al[2] = Al[(tg + 4) * SB + m]; al[3] = Al[(tg + 4) * SB + m + 8];
#pragma unroll
        for (int fn = 0; fn < 4; fn++) {
            mma16(acc[fm][fn], ah[0], ah[1], ah[2], ah[3], bh[fn][0], bh[fn][1]);
            mma16(acc[fm][fn], al[0], al[1], al[2], al[3], bh[fn][0], bh[fn][1]);
            mma16(acc[fm][fn], ah[0], ah[1], ah[2], ah[3], bl[fn][0], bl[fn][1]);
        }
    }
}

// ============================================================================
// 1) kernel predictor GEMM: m = l (cond), n = cout (kw rows), K = 512
// ============================================================================
__global__ __launch_bounds__(256, 2) void kpred_gemm(const float* __restrict__ kw,
                                                     const float* __restrict__ kb,
                                                     const float* __restrict__ cond)
{
    __shared__ __align__(16) uint32_t sAh[2][TILE], sAl[2][TILE];
    __shared__ __align__(16) uint32_t sBh[2][TILE], sBl[2][TILE];
    __shared__ float bsm[128];

    const int b    = blockIdx.x;
    const int mblk = blockIdx.y;
    const int il   = mblk / CKN;
    const int ck   = mblk - il * CKN;
    const int cin  = ck / 3;
    const int kq   = ck - cin * 3;
    const int rbase = il * 49152 + cin * 384 + kq;   // r(cout) = rbase + 3*cout

    const float* condb = cond + (size_t)b * CONDN * LCN;

    const int tid  = threadIdx.x;
    const int wid  = tid >> 5;
    const int lane = tid & 31;
    const int g    = lane >> 2;
    const int tg   = lane & 3;
    const int wm   = wid & 1;
    const int wn   = wid >> 1;

    if (tid < 128) bsm[tid] = kb[rbase + 3 * tid];

    // A (cond): thread owns m=l, k-pairs kpb..kpb+3
    const int al_ = tid & 127, akpb = (tid >> 7) * 4;
    // B (kw rows): thread owns n=row, 8 consecutive k
    const int brow = tid >> 1, bkb = (tid & 1) * 8, bkpb = (tid & 1) * 4;

    float ra[8], rb[8];
    const int NT = CONDN / TK;

    auto ldA = [&](int kc) {
#pragma unroll
        for (int j = 0; j < 4; j++) {
            ra[2 * j]     = condb[(size_t)(kc * TK + 2 * (akpb + j))     * LCN + al_];
            ra[2 * j + 1] = condb[(size_t)(kc * TK + 2 * (akpb + j) + 1) * LCN + al_];
        }
    };
    auto ldB = [&](int kc) {
        const float* p = kw + (size_t)(rbase + 3 * brow) * CONDN + kc * TK + bkb;
        float4 v0 = *(const float4*)p, v1 = *(const float4*)(p + 4);
        rb[0] = v0.x; rb[1] = v0.y; rb[2] = v0.z; rb[3] = v0.w;
        rb[4] = v1.x; rb[5] = v1.y; rb[6] = v1.z; rb[7] = v1.w;
    };
    auto stAB = [&](int buf) {
#pragma unroll
        for (int j = 0; j < 4; j++)
            split_pair(ra[2 * j], ra[2 * j + 1],
                       sAh[buf][(akpb + j) * SB + al_], sAl[buf][(akpb + j) * SB + al_]);
#pragma unroll
        for (int j = 0; j < 4; j++)
            split_pair(rb[2 * j], rb[2 * j + 1],
                       sBh[buf][(bkpb + j) * SB + brow], sBl[buf][(bkpb + j) * SB + brow]);
    };

    float acc[4][4][4];
#pragma unroll
    for (int i = 0; i < 4; i++)
#pragma unroll
        for (int j = 0; j < 4; j++)
#pragma unroll
            for (int q = 0; q < 4; q++) acc[i][j][q] = 0.f;

    ldA(0); ldB(0);
    stAB(0);
    __syncthreads();

    for (int t = 0; t < NT; t++) {
        if (t + 1 < NT) { ldA(t + 1); ldB(t + 1); }
        tile_mma(sAh[t & 1], sAl[t & 1], sBh[t & 1], sBl[t & 1], wm, wn, g, tg, acc);
        if (t + 1 < NT) {
            stAB((t + 1) & 1);
            __syncthreads();
        }
    }

    const size_t base = ((size_t)(b * NLN + il) * LCN) * ((size_t)CKN * HIDN) + (size_t)ck * HIDN;
#pragma unroll
    for (int fm = 0; fm < 4; fm++) {
        const int l0 = wm * 64 + fm * 16 + g;
        float* row0 = g_kbuf + base + (size_t)l0 * (CKN * HIDN);
        float* row1 = row0 + (size_t)8 * (CKN * HIDN);
#pragma unroll
        for (int fn = 0; fn < 4; fn++) {
            const int n0 = wn * 32 + fn * 8 + 2 * tg;
            float b0 = bsm[n0], b1 = bsm[n0 + 1];
            float2 v0, v1;
            v0.x = acc[fm][fn][0] + b0; v0.y = acc[fm][fn][1] + b1;
            v1.x = acc[fm][fn][2] + b0; v1.y = acc[fm][fn][3] + b1;
            *(float2*)(row0 + n0) = v0;
            *(float2*)(row1 + n0) = v1;
        }
    }
}

// ============================================================================
// 2) bias predictor
// ============================================================================
__global__ void bias_pred(const float* __restrict__ bw, const float* __restrict__ bb,
                          const float* __restrict__ cond)
{
    __shared__ float ws[CONDN];
    const int r = blockIdx.x, b = blockIdx.y;
    const int l = threadIdx.x;
    for (int c = l; c < CONDN; c += 128) ws[c] = bw[(size_t)r * CONDN + c];
    __syncthreads();
    const float* condb = cond + (size_t)b * CONDN * LCN + l;
    float acc = bb[r];
#pragma unroll 8
    for (int c = 0; c < CONDN; c++) acc += ws[c] * condb[(size_t)c * LCN];
    g_bbuf[((size_t)b * (NLN * HIDN) + r) * LCN + l] = acc;
}

// ============================================================================
// 4) preconv
// ============================================================================
__global__ void preconv(const float* __restrict__ x, const float* __restrict__ pw,
                        const float* __restrict__ pb)
{
    int idx = blockIdx.x * blockDim.x + threadIdx.x;
    const int T4 = TN / 4;
    int t4 = idx % T4;
    int ch = (idx / T4) & (HIDN - 1);
    int b  = idx / (T4 * HIDN);
    float w = pw[ch], bi = pb[ch];
    float4 xv = *(const float4*)(x + (size_t)b * TN + (size_t)t4 * 4);
    float4 o;
    o.x = lrelu(w * xv.x + bi, 0.2f);
    o.y = lrelu(w * xv.y + bi, 0.2f);
    o.z = lrelu(w * xv.z + bi, 0.2f);
    o.w = lrelu(w * xv.w + bi, 0.2f);
    *(float4*)(g_h0 + ((size_t)(b * HIDN + ch)) * TN + (size_t)t4 * 4) = o;
}

// ============================================================================
// shared conv body: D[o][s] = sum_ck A[o][ck] * H[ck -> (cin, t0+s+(k-1)*d)]
//   A_GATHER=true: A from g_kbuf [ck][cout] (gather);  false: A = W rows [o][ck]
// ============================================================================
template <bool A_GATHER>
__device__ __forceinline__ void conv_body(const float* __restrict__ Wb,
                                          const float* __restrict__ hb,
                                          float* __restrict__ outp,
                                          const float* __restrict__ biasv,
                                          int t0, int d)
{
    __shared__ __align__(16) uint32_t sAh[2][TILE], sAl[2][TILE];
    __shared__ __align__(16) uint32_t sBh[2][TILE], sBl[2][TILE];

    const int tid  = threadIdx.x;
    const int wid  = tid >> 5;
    const int lane = tid & 31;
    const int g    = lane >> 2;
    const int tg   = lane & 3;
    const int wm   = wid & 1;
    const int wn   = wid >> 1;

    // A coords
    const int am   = tid & 127, akpb = (tid >> 7) * 4;          // gather form
    const int arow = tid >> 1,  akb = (tid & 1) * 8, akpb2 = (tid & 1) * 4; // row form
    // B coords
    const int bs = tid & 127, bkpb = (tid >> 7) * 4;

    float ra[8], rb[8];
    const int NT = CKN / TK;

    auto ldA = [&](int kc) {
        if (A_GATHER) {
#pragma unroll
            for (int j = 0; j < 4; j++) {
                ra[2 * j]     = Wb[(size_t)(kc * TK + 2 * (akpb + j))     * HIDN + am];
                ra[2 * j + 1] = Wb[(size_t)(kc * TK + 2 * (akpb + j) + 1) * HIDN + am];
            }
        } else {
            const float* p = Wb + (size_t)arow * CKN + kc * TK + akb;
            float4 v0 = *(const float4*)p, v1 = *(const float4*)(p + 4);
            ra[0] = v0.x; ra[1] = v0.y; ra[2] = v0.z; ra[3] = v0.w;
            ra[4] = v1.x; ra[5] = v1.y; ra[6] = v1.z; ra[7] = v1.w;
        }
    };
    auto ldB = [&](int kc) {
#pragma unroll
        for (int it = 0; it < 8; it++) {
            int ck = kc * TK + 2 * bkpb + it;
            int cin = ck / 3, k = ck - cin * 3;
            int t = t0 + bs + (k - 1) * d;
            rb[it] = (t >= 0 && t < TN) ? hb[(size_t)cin * TN + t] : 0.f;
        }
    };
    auto stAB = [&](int buf) {
        if (A_GATHER) {
#pragma unroll
            for (int j = 0; j < 4; j++)
                split_pair(ra[2 * j], ra[2 * j + 1],
                           sAh[buf][(akpb + j) * SB + am], sAl[buf][(akpb + j) * SB + am]);
        } else {
#pragma unroll
            for (int j = 0; j < 4; j++)
                split_pair(ra[2 * j], ra[2 * j + 1],
                           sAh[buf][(akpb2 + j) * SB + arow], sAl[buf][(akpb2 + j) * SB + arow]);
        }
#pragma unroll
        for (int j = 0; j < 4; j++)
            split_pair(rb[2 * j], rb[2 * j + 1],
                       sBh[buf][(bkpb + j) * SB + bs], sBl[buf][(bkpb + j) * SB + bs]);
    };

    float acc[4][4][4];
#pragma unroll
    for (int i = 0; i < 4; i++)
#pragma unroll
        for (int j = 0; j < 4; j++)
#pragma unroll
            for (int q = 0; q < 4; q++) acc[i][j][q] = 0.f;

    ldA(0); ldB(0);
    stAB(0);
    __syncthreads();

    for (int t = 0; t < NT; t++) {
        if (t + 1 < NT) { ldA(t + 1); ldB(t + 1); }
        tile_mma(sAh[t & 1], sAl[t & 1], sBh[t & 1], sBl[t & 1], wm, wn, g, tg, acc);
        if (t + 1 < NT) {
            stAB((t + 1) & 1);
            __syncthreads();
        }
    }

#pragma unroll
    for (int fm = 0; fm < 4; fm++) {
        const int o0 = wm * 64 + fm * 16 + g;
        float b0 = biasv[o0], b1 = biasv[o0 + 8];
        float* row0 = outp + (size_t)o0 * TN + t0;
        float* row1 = row0 + (size_t)8 * TN;
#pragma unroll
        for (int fn = 0; fn < 4; fn++) {
            const int n0 = wn * 32 + fn * 8 + 2 * tg;
            float2 v0, v1;
            v0.x = lrelu(acc[fm][fn][0] + b0, 3.f);
            v0.y = lrelu(acc[fm][fn][1] + b0, 3.f);
            v1.x = lrelu(acc[fm][fn][2] + b1, 3.f);
            v1.y = lrelu(acc[fm][fn][3] + b1, 3.f);
            *(float2*)(row0 + n0) = v0;
            *(float2*)(row1 + n0) = v1;
        }
    }
}

// 5) LVC: g_h0 -> g_h1
__global__ __launch_bounds__(256, 2) void lvc_gemm(int il)
{
    __shared__ float bsm[128];
    const int sh = blockIdx.x, l = blockIdx.y, b = blockIdx.z;
    const int t0 = l * HOPN + sh * 128;
    if (threadIdx.x < 128)
        bsm[threadIdx.x] = g_bbuf[((size_t)b * (NLN * HIDN) + il * HIDN + threadIdx.x) * LCN + l];
    __syncthreads();

    const float* Wb = g_kbuf + ((size_t)(b * NLN + il) * LCN + l) * ((size_t)CKN * HIDN);
    conv_body<true>(Wb, g_h0 + (size_t)b * HIDN * TN,
                    g_h1 + (size_t)b * HIDN * TN, bsm, t0, 1);
}

// 6) dilated conv: g_h1 -> g_h0  (A = block_w rows, K-major native)
__global__ __launch_bounds__(256, 2) void dil_gemm(int il, int d,
                                                   const float* __restrict__ blockw,
                                                   const float* __restrict__ blockb)
{
    __shared__ float bsm[128];
    const int t0 = blockIdx.x * 128, b = blockIdx.y;
    if (threadIdx.x < 128) bsm[threadIdx.x] = blockb[il * HIDN + threadIdx.x];
    __syncthreads();

    conv_body<false>(blockw + (size_t)il * HIDN * CKN, g_h1 + (size_t)b * HIDN * TN,
                     g_h0 + (size_t)b * HIDN * TN, bsm, t0, d);
}

// ============================================================================
// 7) postconv
// ============================================================================
__global__ void postconv(const float* __restrict__ pw, const float* __restrict__ pb,
                         float* __restrict__ out)
{
    __shared__ float ws[HIDN];
    const int t = blockIdx.x * 256 + threadIdx.x;
    const int b = blockIdx.y;
    if (threadIdx.x < HIDN) ws[threadIdx.x] = pw[threadIdx.x];
    __syncthreads();
    float acc = pb[0];
    const float* hb = g_h0 + (size_t)b * HIDN * TN + t;
#pragma unroll 8
    for (int o = 0; o < HIDN; o++) acc += ws[o] * hb[(size_t)o * TN];
    out[(size_t)b * TN + t] = acc;
}

// ============================================================================
extern "C" void kernel_launch(void* const* d_in, const int* in_sizes, int n_in,
                              void* d_out, int out_size)
{
    const float* x        = (const float*)d_in[0];
    const float* c        = (const float*)d_in[1];
    const float* kernel_w = (const float*)d_in[2];
    const float* kernel_b = (const float*)d_in[3];
    const float* biasp_w  = (const float*)d_in[4];
    const float* biasp_b  = (const float*)d_in[5];
    const float* pre_w    = (const float*)d_in[6];
    const float* pre_b    = (const float*)d_in[7];
    const float* block_w  = (const float*)d_in[8];
    const float* block_b  = (const float*)d_in[9];
    const float* post_w   = (const float*)d_in[10];
    const float* post_b   = (const float*)d_in[11];
    float* out = (float*)d_out;

    kpred_gemm<<<dim3(BN, NLN * CKN), 256>>>(kernel_w, kernel_b, c);
    bias_pred<<<dim3(NLN * HIDN, BN), 128>>>(biasp_w, biasp_b, c);
    preconv<<<(BN * HIDN * TN / 4) / 256, 256>>>(x, pre_w, pre_b);

    const int dils[NLN] = {1, 3, 9, 27};
    for (int i = 0; i < NLN; i++) {
        lvc_gemm<<<dim3(2, LCN, BN), 256>>>(i);
        dil_gemm<<<dim3(TN / 128, BN), 256>>>(i, dils[i], block_w, block_b);
    }
    postconv<<<dim3(TN / 256, BN), 256>>>(post_w, post_b, out);
}

// round 13
// speedup vs baseline: 2.5071x; 1.2366x over previous
#include <cuda_runtime.h>
#include <cuda_fp16.h>
#include <cstdint>

// ---------------- problem constants ----------------
#define BN    4
#define TN    32768
#define LCN   128
#define HOPN  256
#define HIDN  128
#define NLN   4
#define CONDN 512
#define CKN   384
#define TK    16              // K per staged tile (one m16n8k16 step)
#define RS    12              // u32 per m-row (8 data + 4 pad; conflict-free STS.128 & ldmatrix)
#define TILE_U32 (128 * RS)   // 1536 u32 = 6144 B per (operand, half) tile
#define TILE_BYTES (TILE_U32 * 4)

// ---------------- scratch ----------------
__device__ __align__(128) float g_kbuf[(size_t)BN * NLN * LCN * CKN * HIDN]; // [b][il][l][ck][cout]
__device__ __align__(128) float g_bbuf[BN * NLN * HIDN * LCN];
__device__ __align__(128) float g_h0[(size_t)BN * HIDN * TN];
__device__ __align__(128) float g_h1[(size_t)BN * HIDN * TN];

__device__ __forceinline__ float lrelu(float v, float s) { return v >= 0.f ? v : s * v; }

// fp32 -> fp16 hi + fp16 lo (pairwise, packed half2 as u32)
__device__ __forceinline__ void split_pair(float x0, float x1, uint32_t& hi, uint32_t& lo)
{
    __half h0 = __float2half_rn(x0), h1 = __float2half_rn(x1);
    __half l0 = __float2half_rn(x0 - __half2float(h0));
    __half l1 = __float2half_rn(x1 - __half2float(h1));
    __half2 hh = __halves2half2(h0, h1);
    __half2 ll = __halves2half2(l0, l1);
    hi = *(uint32_t*)&hh;
    lo = *(uint32_t*)&ll;
}

__device__ __forceinline__ void mma16(float* c, uint32_t a0, uint32_t a1, uint32_t a2, uint32_t a3,
                                      uint32_t b0, uint32_t b1)
{
    asm volatile(
        "mma.sync.aligned.m16n8k16.row.col.f32.f16.f16.f32 "
        "{%0,%1,%2,%3}, {%4,%5,%6,%7}, {%8,%9}, {%0,%1,%2,%3};\n"
        : "+f"(c[0]), "+f"(c[1]), "+f"(c[2]), "+f"(c[3])
        : "r"(a0), "r"(a1), "r"(a2), "r"(a3), "r"(b0), "r"(b1));
}

__device__ __forceinline__ void ldm4(uint32_t* r, uint32_t addr)
{
    asm volatile("ldmatrix.sync.aligned.m8n8.x4.shared.b16 {%0,%1,%2,%3}, [%4];"
                 : "=r"(r[0]), "=r"(r[1]), "=r"(r[2]), "=r"(r[3]) : "r"(addr));
}

// smem layout per stage s (0/1): tiles at (s*4 + t)*TILE_U32, t: 0=Ah 1=Al 2=Bh 3=Bl.
// A tile rows = m (0..127), B tile rows = n; each row: 8 data u32 (16 halves) + 4 pad.
// Bias vector lives in pad col 8: sm[i*RS + 8].

// producer store: split 8 fp32 per operand -> hi/lo uint4 -> STS.128
__device__ __forceinline__ void st_tiles(uint32_t* sm, int stage, int prow, int pkp,
                                         const float* va, const float* vb)
{
    uint32_t* p = sm + stage * 4 * TILE_U32 + prow * RS + pkp;
    uint4 h, l;
    split_pair(va[0], va[1], h.x, l.x); split_pair(va[2], va[3], h.y, l.y);
    split_pair(va[4], va[5], h.z, l.z); split_pair(va[6], va[7], h.w, l.w);
    *(uint4*)(p)                = h;
    *(uint4*)(p + TILE_U32)     = l;
    split_pair(vb[0], vb[1], h.x, l.x); split_pair(vb[2], vb[3], h.y, l.y);
    split_pair(vb[4], vb[5], h.z, l.z); split_pair(vb[6], vb[7], h.w, l.w);
    *(uint4*)(p + 2 * TILE_U32) = h;
    *(uint4*)(p + 3 * TILE_U32) = l;
}

// consumer: one 128x128 x K=16 tile, 3-product fp16 split, ldmatrix fragments
__device__ __forceinline__ void mma_tile(uint32_t smb, int stage, uint32_t loA, uint32_t loB,
                                         float (&acc)[4][4][4])
{
    const uint32_t base = smb + (uint32_t)stage * 4 * TILE_BYTES;
    uint32_t bh[4][2], bl[4][2];
    ldm4(&bh[0][0], base + 2 * TILE_BYTES + loB);
    ldm4(&bh[2][0], base + 2 * TILE_BYTES + loB + 16 * 48);
    ldm4(&bl[0][0], base + 3 * TILE_BYTES + loB);
    ldm4(&bl[2][0], base + 3 * TILE_BYTES + loB + 16 * 48);
#pragma unroll
    for (int fm = 0; fm < 4; fm++) {
        uint32_t ah[4], al[4];
        ldm4(ah, base + loA + fm * 16 * 48);
        ldm4(al, base + TILE_BYTES + loA + fm * 16 * 48);
#pragma unroll
        for (int fn = 0; fn < 4; fn++) {
            mma16(acc[fm][fn], ah[0], ah[1], ah[2], ah[3], bh[fn][0], bh[fn][1]);
            mma16(acc[fm][fn], al[0], al[1], al[2], al[3], bh[fn][0], bh[fn][1]);
            mma16(acc[fm][fn], ah[0], ah[1], ah[2], ah[3], bl[fn][0], bl[fn][1]);
        }
    }
}

// lane byte-offsets for ldmatrix addressing
__device__ __forceinline__ uint32_t laneoff_A(int lane, int wm)
{
    int m = (lane & 7) + ((lane >> 3) & 1) * 8 + wm * 64;
    return (uint32_t)(m * 48 + (lane >> 4) * 16);
}
__device__ __forceinline__ uint32_t laneoff_B(int lane, int wn)
{
    int n = ((lane >> 4) * 8) + (lane & 7) + wn * 32;
    return (uint32_t)(n * 48 + ((lane >> 3) & 1) * 16);
}

// ============================================================================
// 1) kernel predictor GEMM: m = l (cond gather), n = cout (kw rows), K = 512
// ============================================================================
__global__ __launch_bounds__(256, 2) void kpred_gemm(const float* __restrict__ kw,
                                                     const float* __restrict__ kb,
                                                     const float* __restrict__ cond)
{
    __shared__ __align__(16) uint32_t sm[8 * TILE_U32];   // 48 KB

    const int b    = blockIdx.x;
    const int mblk = blockIdx.y;
    const int il   = mblk / CKN;
    const int ck   = mblk - il * CKN;
    const int cin  = ck / 3;
    const int kq   = ck - cin * 3;
    const int rbase = il * 49152 + cin * 384 + kq;   // r(cout) = rbase + 3*cout

    const float* condb = cond + (size_t)b * CONDN * LCN;

    const int tid  = threadIdx.x;
    const int wid  = tid >> 5;
    const int lane = tid & 31;
    const int g    = lane >> 2;
    const int tg   = lane & 3;
    const int wm   = wid & 1;
    const int wn   = wid >> 1;

    if (tid < 128) sm[tid * RS + 8] = __float_as_uint(kb[rbase + 3 * tid]);

    const int prow = tid & 127;          // A: m=l ; B: n=cout row
    const int pkp  = (tid >> 7) * 4;     // k-pair base (0 or 4)
    const uint32_t smb = (uint32_t)__cvta_generic_to_shared(sm);
    const uint32_t loA = laneoff_A(lane, wm);
    const uint32_t loB = laneoff_B(lane, wn);

    float ra[8], rb[8];
    const int NT = CONDN / TK;

    auto ldA = [&](int kc) {
#pragma unroll
        for (int j = 0; j < 8; j++)
            ra[j] = condb[(size_t)(kc * TK + pkp * 2 + j) * LCN + prow];
    };
    auto ldB = [&](int kc) {
        const float* p = kw + (size_t)(rbase + 3 * prow) * CONDN + kc * TK + pkp * 2;
        float4 v0 = *(const float4*)p, v1 = *(const float4*)(p + 4);
        rb[0] = v0.x; rb[1] = v0.y; rb[2] = v0.z; rb[3] = v0.w;
        rb[4] = v1.x; rb[5] = v1.y; rb[6] = v1.z; rb[7] = v1.w;
    };

    float acc[4][4][4];
#pragma unroll
    for (int i = 0; i < 4; i++)
#pragma unroll
        for (int j = 0; j < 4; j++)
#pragma unroll
            for (int q = 0; q < 4; q++) acc[i][j][q] = 0.f;

    ldA(0); ldB(0);
    st_tiles(sm, 0, prow, pkp, ra, rb);
    __syncthreads();

    for (int t = 0; t < NT; t++) {
        if (t + 1 < NT) { ldA(t + 1); ldB(t + 1); }
        mma_tile(smb, t & 1, loA, loB, acc);
        if (t + 1 < NT) {
            st_tiles(sm, (t + 1) & 1, prow, pkp, ra, rb);
            __syncthreads();
        }
    }

    const size_t base = ((size_t)(b * NLN + il) * LCN) * ((size_t)CKN * HIDN) + (size_t)ck * HIDN;
#pragma unroll
    for (int fm = 0; fm < 4; fm++) {
        const int l0 = wm * 64 + fm * 16 + g;
        float* row0 = g_kbuf + base + (size_t)l0 * (CKN * HIDN);
        float* row1 = row0 + (size_t)8 * (CKN * HIDN);
#pragma unroll
        for (int fn = 0; fn < 4; fn++) {
            const int n0 = wn * 32 + fn * 8 + 2 * tg;
            float b0 = __uint_as_float(sm[n0 * RS + 8]);
            float b1 = __uint_as_float(sm[(n0 + 1) * RS + 8]);
            float2 v0, v1;
            v0.x = acc[fm][fn][0] + b0; v0.y = acc[fm][fn][1] + b1;
            v1.x = acc[fm][fn][2] + b0; v1.y = acc[fm][fn][3] + b1;
            *(float2*)(row0 + n0) = v0;
            *(float2*)(row1 + n0) = v1;
        }
    }
}

// ============================================================================
// 2) bias predictor
// ============================================================================
__global__ void bias_pred(const float* __restrict__ bw, const float* __restrict__ bb,
                          const float* __restrict__ cond)
{
    __shared__ float ws[CONDN];
    const int r = blockIdx.x, b = blockIdx.y;
    const int l = threadIdx.x;
    for (int c = l; c < CONDN; c += 128) ws[c] = bw[(size_t)r * CONDN + c];
    __syncthreads();
    const float* condb = cond + (size_t)b * CONDN * LCN + l;
    float acc = bb[r];
#pragma unroll 8
    for (int c = 0; c < CONDN; c++) acc += ws[c] * condb[(size_t)c * LCN];
    g_bbuf[((size_t)b * (NLN * HIDN) + r) * LCN + l] = acc;
}

// ============================================================================
// 4) preconv
// ============================================================================
__global__ void preconv(const float* __restrict__ x, const float* __restrict__ pw,
                        const float* __restrict__ pb)
{
    int idx = blockIdx.x * blockDim.x + threadIdx.x;
    const int T4 = TN / 4;
    int t4 = idx % T4;
    int ch = (idx / T4) & (HIDN - 1);
    int b  = idx / (T4 * HIDN);
    float w = pw[ch], bi = pb[ch];
    float4 xv = *(const float4*)(x + (size_t)b * TN + (size_t)t4 * 4);
    float4 o;
    o.x = lrelu(w * xv.x + bi, 0.2f);
    o.y = lrelu(w * xv.y + bi, 0.2f);
    o.z = lrelu(w * xv.z + bi, 0.2f);
    o.w = lrelu(w * xv.w + bi, 0.2f);
    *(float4*)(g_h0 + ((size_t)(b * HIDN + ch)) * TN + (size_t)t4 * 4) = o;
}

// ============================================================================
// shared conv body: D[o][s] = sum_ck A[o][ck] * H[(cin, t0+s+(k-1)*d)]
//   A_GATHER=true: A from g_kbuf [ck][cout] (strided gather); false: A = W rows [o][ck]
//   bias already parked in sm pad col 8 by caller.
// ============================================================================
template <bool A_GATHER>
__device__ __forceinline__ void conv_body(uint32_t* sm,
                                          const float* __restrict__ Wb,
                                          const float* __restrict__ hb,
                                          float* __restrict__ outp,
                                          int t0, int d)
{
    const int tid  = threadIdx.x;
    const int wid  = tid >> 5;
    const int lane = tid & 31;
    const int g    = lane >> 2;
    const int tg   = lane & 3;
    const int wm   = wid & 1;
    const int wn   = wid >> 1;

    const int prow = tid & 127;
    const int pkp  = (tid >> 7) * 4;
    const uint32_t smb = (uint32_t)__cvta_generic_to_shared(sm);
    const uint32_t loA = laneoff_A(lane, wm);
    const uint32_t loB = laneoff_B(lane, wn);

    float ra[8], rb[8];
    const int NT = CKN / TK;

    auto ldA = [&](int kc) {
        if (A_GATHER) {
#pragma unroll
            for (int j = 0; j < 8; j++)
                ra[j] = Wb[(size_t)(kc * TK + pkp * 2 + j) * HIDN + prow];
        } else {
            const float* p = Wb + (size_t)prow * CKN + kc * TK + pkp * 2;
            float4 v0 = *(const float4*)p, v1 = *(const float4*)(p + 4);
            ra[0] = v0.x; ra[1] = v0.y; ra[2] = v0.z; ra[3] = v0.w;
            ra[4] = v1.x; ra[5] = v1.y; ra[6] = v1.z; ra[7] = v1.w;
        }
    };
    auto ldB = [&](int kc) {
#pragma unroll
        for (int j = 0; j < 8; j++) {
            int ck = kc * TK + pkp * 2 + j;
            int cin = ck / 3, k = ck - cin * 3;
            int t = t0 + prow + (k - 1) * d;
            rb[j] = (t >= 0 && t < TN) ? hb[(size_t)cin * TN + t] : 0.f;
        }
    };

    float acc[4][4][4];
#pragma unroll
    for (int i = 0; i < 4; i++)
#pragma unroll
        for (int j = 0; j < 4; j++)
#pragma unroll
            for (int q = 0; q < 4; q++) acc[i][j][q] = 0.f;

    ldA(0); ldB(0);
    st_tiles(sm, 0, prow, pkp, ra, rb);
    __syncthreads();

    for (int t = 0; t < NT; t++) {
        if (t + 1 < NT) { ldA(t + 1); ldB(t + 1); }
        mma_tile(smb, t & 1, loA, loB, acc);
        if (t + 1 < NT) {
            st_tiles(sm, (t + 1) & 1, prow, pkp, ra, rb);
            __syncthreads();
        }
    }

#pragma unroll
    for (int fm = 0; fm < 4; fm++) {
        const int o0 = wm * 64 + fm * 16 + g;
        float b0 = __uint_as_float(sm[o0 * RS + 8]);
        float b1 = __uint_as_float(sm[(o0 + 8) * RS + 8]);
        float* row0 = outp + (size_t)o0 * TN + t0;
        float* row1 = row0 + (size_t)8 * TN;
#pragma unroll
        for (int fn = 0; fn < 4; fn++) {
            const int n0 = wn * 32 + fn * 8 + 2 * tg;
            float2 v0, v1;
            v0.x = lrelu(acc[fm][fn][0] + b0, 3.f);
            v0.y = lrelu(acc[fm][fn][1] + b0, 3.f);
            v1.x = lrelu(acc[fm][fn][2] + b1, 3.f);
            v1.y = lrelu(acc[fm][fn][3] + b1, 3.f);
            *(float2*)(row0 + n0) = v0;
            *(float2*)(row1 + n0) = v1;
        }
    }
}

// 5) LVC: g_h0 -> g_h1
__global__ __launch_bounds__(256, 2) void lvc_gemm(int il)
{
    __shared__ __align__(16) uint32_t sm[8 * TILE_U32];
    const int sh = blockIdx.x, l = blockIdx.y, b = blockIdx.z;
    const int t0 = l * HOPN + sh * 128;
    if (threadIdx.x < 128)
        sm[threadIdx.x * RS + 8] = __float_as_uint(
            g_bbuf[((size_t)b * (NLN * HIDN) + il * HIDN + threadIdx.x) * LCN + l]);

    const float* Wb = g_kbuf + ((size_t)(b * NLN + il) * LCN + l) * ((size_t)CKN * HIDN);
    conv_body<true>(sm, Wb, g_h0 + (size_t)b * HIDN * TN,
                    g_h1 + (size_t)b * HIDN * TN, t0, 1);
}

// 6) dilated conv: g_h1 -> g_h0  (A = block_w rows, K-major native)
__global__ __launch_bounds__(256, 2) void dil_gemm(int il, int d,
                                                   const float* __restrict__ blockw,
                                                   const float* __restrict__ blockb)
{
    __shared__ __align__(16) uint32_t sm[8 * TILE_U32];
    const int t0 = blockIdx.x * 128, b = blockIdx.y;
    if (threadIdx.x < 128)
        sm[threadIdx.x * RS + 8] = __float_as_uint(blockb[il * HIDN + threadIdx.x]);

    conv_body<false>(sm, blockw + (size_t)il * HIDN * CKN, g_h1 + (size_t)b * HIDN * TN,
                     g_h0 + (size_t)b * HIDN * TN, t0, d);
}

// ============================================================================
// 7) postconv
// ============================================================================
__global__ void postconv(const float* __restrict__ pw, const float* __restrict__ pb,
                         float* __restrict__ out)
{
    __shared__ float ws[HIDN];
    const int t = blockIdx.x * 256 + threadIdx.x;
    const int b = blockIdx.y;
    if (threadIdx.x < HIDN) ws[threadIdx.x] = pw[threadIdx.x];
    __syncthreads();
    float acc = pb[0];
    const float* hb = g_h0 + (size_t)b * HIDN * TN + t;
#pragma unroll 8
    for (int o = 0; o < HIDN; o++) acc += ws[o] * hb[(size_t)o * TN];
    out[(size_t)b * TN + t] = acc;
}

// ============================================================================
extern "C" void kernel_launch(void* const* d_in, const int* in_sizes, int n_in,
                              void* d_out, int out_size)
{
    const float* x        = (const float*)d_in[0];
    const float* c        = (const float*)d_in[1];
    const float* kernel_w = (const float*)d_in[2];
    const float* kernel_b = (const float*)d_in[3];
    const float* biasp_w  = (const float*)d_in[4];
    const float* biasp_b  = (const float*)d_in[5];
    const float* pre_w    = (const float*)d_in[6];
    const float* pre_b    = (const float*)d_in[7];
    const float* block_w  = (const float*)d_in[8];
    const float* block_b  = (const float*)d_in[9];
    const float* post_w   = (const float*)d_in[10];
    const float* post_b   = (const float*)d_in[11];
    float* out = (float*)d_out;

    kpred_gemm<<<dim3(BN, NLN * CKN), 256>>>(kernel_w, kernel_b, c);
    bias_pred<<<dim3(NLN * HIDN, BN), 128>>>(biasp_w, biasp_b, c);
    preconv<<<(BN * HIDN * TN / 4) / 256, 256>>>(x, pre_w, pre_b);

    const int dils[NLN] = {1, 3, 9, 27};
    for (int i = 0; i < NLN; i++) {
        lvc_gemm<<<dim3(2, LCN, BN), 256>>>(i);
        dil_gemm<<<dim3(TN / 128, BN), 256>>>(i, dils[i], block_w, block_b);
    }
    postconv<<<dim3(TN / 256, BN), 256>>>(post_w, post_b, out);
}